// round 1
// baseline (speedup 1.0000x reference)
#include <cuda_runtime.h>
#include <math.h>

#define T_LEN 1024
#define DIM_  1024
#define DI    2048
#define DS    16

// ---------------- scratch (no allocations allowed) ----------------
__device__ float g_xz[T_LEN * 4096];        // in_proj output: [x_in | gate]
__device__ float g_xc[T_LEN * DI];          // conv+silu output (per scale, reused)
__device__ float g_proj[T_LEN * 32];        // [B | C] per scale (reused)
__device__ float g_dt[T_LEN * DI];          // dt per scale (reused)
__device__ float g_out0[T_LEN * DI];
__device__ float g_out1[(T_LEN / 2) * DI];
__device__ float g_out2[(T_LEN / 4) * DI];
__device__ float g_fused[T_LEN * DI];
__device__ float g_ctx[T_LEN * DI];
__device__ float g_g1[T_LEN * DIM_];
__device__ float g_gctx[T_LEN * DI];
__device__ float g_u[T_LEN * DI];
__device__ float g_o[T_LEN * DIM_];
__device__ float g_scr[2 * T_LEN * DIM_];   // split-K partials

// ---------------- helpers ----------------
__device__ __forceinline__ float sigmoidf_(float x) { return 1.f / (1.f + __expf(-x)); }
__device__ __forceinline__ float siluf_(float x)    { return x * sigmoidf_(x); }
__device__ __forceinline__ float softplusf_(float x) {
    if (x > 20.f) return x;
    return log1pf(__expf(x));
}

// ---------------- SGEMM: C[m,n] = sum_k A[m,k]*B[n,k]  (both k-contiguous) ----
// 128x128 tile, BK=8, 8x8 per thread, 256 threads. Optional split-K over
// blockIdx.z: each z handles Kper columns starting at z*Kper, writing to
// C + z*czstride (partials combined by a separate kernel).
__global__ void __launch_bounds__(256) sgemm_nt(
    const float* __restrict__ A, int lda,
    const float* __restrict__ B, int ldb,
    float* __restrict__ C, int ldc,
    int Kper, size_t czstride)
{
    __shared__ float As[8][128];
    __shared__ float Bs[8][128];

    const int kz = blockIdx.z;
    A += (size_t)kz * Kper;
    B += (size_t)kz * Kper;
    C += (size_t)kz * czstride;

    const int tid  = threadIdx.x;
    const int bm   = blockIdx.y * 128;
    const int bn   = blockIdx.x * 128;
    const int tx   = tid & 15;
    const int ty   = tid >> 4;
    const int lrow = tid >> 1;
    const int lcol = (tid & 1) * 4;

    const float* Aptr = A + (size_t)(bm + lrow) * lda + lcol;
    const float* Bptr = B + (size_t)(bn + lrow) * ldb + lcol;

    float acc[8][8];
#pragma unroll
    for (int i = 0; i < 8; i++)
#pragma unroll
        for (int j = 0; j < 8; j++) acc[i][j] = 0.f;

    for (int k0 = 0; k0 < Kper; k0 += 8) {
        float4 a4 = *reinterpret_cast<const float4*>(Aptr + k0);
        float4 b4 = *reinterpret_cast<const float4*>(Bptr + k0);
        As[lcol + 0][lrow] = a4.x; As[lcol + 1][lrow] = a4.y;
        As[lcol + 2][lrow] = a4.z; As[lcol + 3][lrow] = a4.w;
        Bs[lcol + 0][lrow] = b4.x; Bs[lcol + 1][lrow] = b4.y;
        Bs[lcol + 2][lrow] = b4.z; Bs[lcol + 3][lrow] = b4.w;
        __syncthreads();
#pragma unroll
        for (int kk = 0; kk < 8; kk++) {
            float a[8], b[8];
#pragma unroll
            for (int i = 0; i < 8; i++) a[i] = As[kk][ty * 8 + i];
#pragma unroll
            for (int j = 0; j < 8; j++) b[j] = Bs[kk][tx * 8 + j];
#pragma unroll
            for (int i = 0; i < 8; i++)
#pragma unroll
                for (int j = 0; j < 8; j++) acc[i][j] += a[i] * b[j];
        }
        __syncthreads();
    }

#pragma unroll
    for (int i = 0; i < 8; i++) {
        float* crow = C + (size_t)(bm + ty * 8 + i) * ldc + bn + tx * 8;
#pragma unroll
        for (int j = 0; j < 8; j += 4) {
            float4 v = make_float4(acc[i][j], acc[i][j + 1], acc[i][j + 2], acc[i][j + 3]);
            *reinterpret_cast<float4*>(crow + j) = v;
        }
    }
}

// ---------------- downsample + causal depthwise conv + SiLU -------------
__global__ void conv_silu_kernel(const float* __restrict__ xz,
                                 const float* __restrict__ cw,
                                 const float* __restrict__ cb,
                                 float* __restrict__ xc,
                                 int T, int stride)
{
    int idx = blockIdx.x * blockDim.x + threadIdx.x;
    if (idx >= T * DI) return;
    int t = idx >> 11;
    int d = idx & (DI - 1);
    float4 w4 = *reinterpret_cast<const float4*>(cw + d * 4);
    float wk[4] = {w4.x, w4.y, w4.z, w4.w};
    float acc = cb[d];
    float inv = 1.f / (float)stride;
#pragma unroll
    for (int k = 0; k < 4; k++) {
        int tt = t - 3 + k;
        if (tt >= 0) {
            float v = 0.f;
            int base = tt * stride;
            for (int r = 0; r < stride; r++) v += xz[(size_t)(base + r) * 4096 + d];
            acc += wk[k] * (v * inv);
        }
    }
    xc[idx] = siluf_(acc);
}

// ---------------- xc @ xproj_w.T -> proj[T,32]  (B|C) --------------------
__global__ void xproj_kernel(const float* __restrict__ xc,
                             const float* __restrict__ W,   // [32, DI]
                             float* __restrict__ proj)
{
    int t = blockIdx.x;
    __shared__ float sx[DI];
    for (int i = threadIdx.x; i < DI; i += 256) sx[i] = xc[(size_t)t * DI + i];
    __syncthreads();
    int warp = threadIdx.x >> 5, lane = threadIdx.x & 31;
    for (int j = warp; j < 32; j += 8) {
        const float* w = W + (size_t)j * DI;
        float s = 0.f;
        for (int i = lane * 4; i < DI; i += 128) {
            float4 a = *reinterpret_cast<const float4*>(&sx[i]);
            float4 b = *reinterpret_cast<const float4*>(&w[i]);
            s += a.x * b.x + a.y * b.y + a.z * b.z + a.w * b.w;
        }
        for (int off = 16; off; off >>= 1) s += __shfl_xor_sync(0xffffffffu, s, off);
        if (!lane) proj[t * 32 + j] = s;
    }
}

// ---------------- dt = softplus(softplus(B @ dtw.T + dtb)) ---------------
__global__ void dtproj_kernel(const float* __restrict__ proj,
                              const float* __restrict__ dtw,  // [DI, 16]
                              const float* __restrict__ dtb,
                              float* __restrict__ dt, int T)
{
    int idx = blockIdx.x * blockDim.x + threadIdx.x;
    if (idx >= T * DI) return;
    int t = idx >> 11;
    int d = idx & (DI - 1);
    const float* bp = proj + t * 32;
    const float4* w4 = reinterpret_cast<const float4*>(dtw + (size_t)d * 16);
    float s = dtb[d];
#pragma unroll
    for (int q = 0; q < 4; q++) {
        float4 w = w4[q];
        s += bp[q * 4 + 0] * w.x + bp[q * 4 + 1] * w.y +
             bp[q * 4 + 2] * w.z + bp[q * 4 + 3] * w.w;
    }
    dt[idx] = softplusf_(softplusf_(s));
}

// ---------------- selective scan (linear-space == reference log-space) ---
// thread = (d, n); n = lane%16. h[t] = clip(dA)*h[t-1] + clip(dBx),
// y[t,d] = sum_n C[t,n]*h[t,d,n] + D[d]*xc[t,d]
__global__ void scan_kernel(const float* __restrict__ dt,
                            const float* __restrict__ proj,
                            const float* __restrict__ xc,
                            const float* __restrict__ Dp,
                            float* __restrict__ y, int T)
{
    int gid = blockIdx.x * blockDim.x + threadIdx.x;   // 0..DI*DS-1
    int n = gid & 15;
    int d = gid >> 4;
    float An = -(float)(n + 1);
    float Dpd = Dp[d];
    float h = 0.f;
    for (int t = 0; t < T; t++) {
        float dtv = dt[(size_t)t * DI + d];
        float xcv = xc[(size_t)t * DI + d];
        float Bv  = proj[t * 32 + n];
        float Cv  = proj[t * 32 + 16 + n];
        float dA  = fmaxf(__expf(dtv * An), 1e-38f);
        float dBx = fmaxf(dtv * Bv * xcv, 1e-38f);
        h = dA * h + dBx;
        float v = Cv * h;
        v += __shfl_xor_sync(0xffffffffu, v, 8);
        v += __shfl_xor_sync(0xffffffffu, v, 4);
        v += __shfl_xor_sync(0xffffffffu, v, 2);
        v += __shfl_xor_sync(0xffffffffu, v, 1);
        if (n == 0) y[(size_t)t * DI + d] = v + Dpd * xcv;
    }
}

// ---------------- upsample + softmax mix + ctx ---------------------------
__device__ __forceinline__ float upsample_read(const float* __restrict__ y,
                                               int Tin, int t, int d)
{
    if (Tin == T_LEN) return y[(size_t)t * DI + d];
    float scale = (float)Tin / (float)T_LEN;
    float pos = ((float)t + 0.5f) * scale - 0.5f;
    pos = fminf(fmaxf(pos, 0.f), (float)(Tin - 1));
    int lo = (int)floorf(pos);
    int hi = min(lo + 1, Tin - 1);
    float w = pos - (float)lo;
    return y[(size_t)lo * DI + d] * (1.f - w) + y[(size_t)hi * DI + d] * w;
}

__global__ void fuse_kernel(const float* __restrict__ y0,
                            const float* __restrict__ y1,
                            const float* __restrict__ y2,
                            const float* __restrict__ sw,
                            float* __restrict__ fused,
                            float* __restrict__ ctx)
{
    int idx = blockIdx.x * blockDim.x + threadIdx.x;
    if (idx >= T_LEN * DI) return;
    int t = idx >> 11, d = idx & (DI - 1);
    float w0 = sw[0], w1 = sw[1], w2 = sw[2];
    float m = fmaxf(w0, fmaxf(w1, w2));
    float e0 = __expf(w0 - m), e1 = __expf(w1 - m), e2 = __expf(w2 - m);
    float inv = 1.f / (e0 + e1 + e2);
    float u0 = y0[idx];
    float u1 = upsample_read(y1, T_LEN / 2, t, d);
    float u2 = upsample_read(y2, T_LEN / 4, t, d);
    fused[idx] = (e0 * u0 + e1 * u1 + e2 * u2) * inv;
    ctx[idx]   = (u0 + u1 + u2) * (1.f / 3.f);
}

// ---------------- split-K combiners --------------------------------------
__global__ void add_silu_kernel(const float* __restrict__ a,
                                const float* __restrict__ b,
                                float* __restrict__ c)
{
    int i = blockIdx.x * blockDim.x + threadIdx.x;
    if (i >= T_LEN * DIM_) return;
    float v = a[i] + b[i];
    c[i] = siluf_(v);
}
__global__ void add_kernel(const float* __restrict__ a,
                           const float* __restrict__ b,
                           float* __restrict__ c)
{
    int i = blockIdx.x * blockDim.x + threadIdx.x;
    if (i >= T_LEN * DIM_) return;
    c[i] = a[i] + b[i];
}

// ---------------- u = fused * sigmoid(gctx) * silu(gate) -----------------
__global__ void u_kernel(const float* __restrict__ fused,
                         const float* __restrict__ gctx,
                         const float* __restrict__ xz,
                         float* __restrict__ u)
{
    int idx = blockIdx.x * blockDim.x + threadIdx.x;
    if (idx >= T_LEN * DI) return;
    int t = idx >> 11, d = idx & (DI - 1);
    float gv = xz[(size_t)t * 4096 + 2048 + d];
    u[idx] = fused[idx] * sigmoidf_(gctx[idx]) * siluf_(gv);
}

// ---------------- residual + LayerNorm -----------------------------------
__global__ void ln_kernel(const float* __restrict__ o,
                          const float* __restrict__ x,
                          const float* __restrict__ g,
                          const float* __restrict__ bb,
                          float* __restrict__ out)
{
    int t = blockIdx.x;
    int tid = threadIdx.x;
    float v[4];
    float s = 0.f, s2 = 0.f;
#pragma unroll
    for (int i = 0; i < 4; i++) {
        int j = tid + i * 256;
        float y = o[(size_t)t * DIM_ + j] + x[(size_t)t * DIM_ + j];
        v[i] = y; s += y; s2 += y * y;
    }
    __shared__ float sh1[8], sh2[8];
    for (int off = 16; off; off >>= 1) {
        s  += __shfl_xor_sync(0xffffffffu, s, off);
        s2 += __shfl_xor_sync(0xffffffffu, s2, off);
    }
    int w = tid >> 5, l = tid & 31;
    if (!l) { sh1[w] = s; sh2[w] = s2; }
    __syncthreads();
    if (w == 0) {
        s  = (l < 8) ? sh1[l] : 0.f;
        s2 = (l < 8) ? sh2[l] : 0.f;
        for (int off = 4; off; off >>= 1) {
            s  += __shfl_xor_sync(0xffffffffu, s, off);
            s2 += __shfl_xor_sync(0xffffffffu, s2, off);
        }
        if (!l) { sh1[0] = s; sh2[0] = s2; }
    }
    __syncthreads();
    float mu  = sh1[0] * (1.f / DIM_);
    float var = sh2[0] * (1.f / DIM_) - mu * mu;
    float inv = rsqrtf(var + 1e-5f);
#pragma unroll
    for (int i = 0; i < 4; i++) {
        int j = tid + i * 256;
        out[(size_t)t * DIM_ + j] = (v[i] - mu) * inv * g[j] + bb[j];
    }
}

// ---------------- launch --------------------------------------------------
extern "C" void kernel_launch(void* const* d_in, const int* in_sizes, int n_in,
                              void* d_out, int out_size)
{
    const float* x        = (const float*)d_in[0];
    const float* in_proj  = (const float*)d_in[1];
    const float* conv_w   = (const float*)d_in[2];
    const float* conv_b   = (const float*)d_in[3];
    const float* xproj_w  = (const float*)d_in[4];
    const float* dtproj_w = (const float*)d_in[5];
    const float* dtproj_b = (const float*)d_in[6];
    const float* D_param  = (const float*)d_in[7];
    const float* sw       = (const float*)d_in[8];
    const float* gate_w1  = (const float*)d_in[9];
    const float* gate_w2  = (const float*)d_in[10];
    const float* out_proj = (const float*)d_in[11];
    const float* ln_g     = (const float*)d_in[12];
    const float* ln_b     = (const float*)d_in[13];
    float* out = (float*)d_out;

    float *xz, *xc, *proj, *dt, *o0, *o1, *o2, *fused, *ctx, *g1, *gctx, *u, *o, *scr;
    cudaGetSymbolAddress((void**)&xz,    g_xz);
    cudaGetSymbolAddress((void**)&xc,    g_xc);
    cudaGetSymbolAddress((void**)&proj,  g_proj);
    cudaGetSymbolAddress((void**)&dt,    g_dt);
    cudaGetSymbolAddress((void**)&o0,    g_out0);
    cudaGetSymbolAddress((void**)&o1,    g_out1);
    cudaGetSymbolAddress((void**)&o2,    g_out2);
    cudaGetSymbolAddress((void**)&fused, g_fused);
    cudaGetSymbolAddress((void**)&ctx,   g_ctx);
    cudaGetSymbolAddress((void**)&g1,    g_g1);
    cudaGetSymbolAddress((void**)&gctx,  g_gctx);
    cudaGetSymbolAddress((void**)&u,     g_u);
    cudaGetSymbolAddress((void**)&o,     g_o);
    cudaGetSymbolAddress((void**)&scr,   g_scr);

    // xz = x @ in_proj_w.T   [1024,1024]x[4096,1024]^T
    sgemm_nt<<<dim3(4096 / 128, T_LEN / 128, 1), 256>>>(x, DIM_, in_proj, DIM_, xz, 4096, DIM_, 0);

    float* outs[3] = {o0, o1, o2};
    for (int s = 0; s < 3; s++) {
        int T = T_LEN >> s;
        int stride = 1 << s;
        conv_silu_kernel<<<(T * DI) / 256, 256>>>(xz, conv_w + s * DI * 4, conv_b + s * DI, xc, T, stride);
        xproj_kernel<<<T, 256>>>(xc, xproj_w + s * 32 * DI, proj);
        dtproj_kernel<<<(T * DI) / 256, 256>>>(proj, dtproj_w + s * DI * DS, dtproj_b + s * DI, dt, T);
        scan_kernel<<<(DI * DS) / 256, 256>>>(dt, proj, xc, D_param + s * DI, outs[s], T);
    }

    fuse_kernel<<<(T_LEN * DI) / 256, 256>>>(o0, o1, o2, sw, fused, ctx);

    // g1 = silu(ctx @ gate_w1.T)  — split-K x2 (K=2048) for occupancy
    sgemm_nt<<<dim3(DIM_ / 128, T_LEN / 128, 2), 256>>>(ctx, DI, gate_w1, DI, scr, DIM_, DI / 2,
                                                        (size_t)T_LEN * DIM_);
    add_silu_kernel<<<(T_LEN * DIM_) / 256, 256>>>(scr, scr + T_LEN * DIM_, g1);

    // gctx_raw = g1 @ gate_w2.T  (sigmoid fused into u_kernel)
    sgemm_nt<<<dim3(DI / 128, T_LEN / 128, 1), 256>>>(g1, DIM_, gate_w2, DIM_, gctx, DI, DIM_, 0);

    u_kernel<<<(T_LEN * DI) / 256, 256>>>(fused, gctx, xz, u);

    // o = u @ out_proj_w.T — split-K x2
    sgemm_nt<<<dim3(DIM_ / 128, T_LEN / 128, 2), 256>>>(u, DI, out_proj, DI, scr, DIM_, DI / 2,
                                                        (size_t)T_LEN * DIM_);
    add_kernel<<<(T_LEN * DIM_) / 256, 256>>>(scr, scr + T_LEN * DIM_, o);

    ln_kernel<<<T_LEN, 256>>>(o, x, ln_g, ln_b, out);
}

// round 5
// speedup vs baseline: 1.4236x; 1.4236x over previous
#include <cuda_runtime.h>
#include <cuda_bf16.h>
#include <cstdint>
#include <math.h>

#define T_LEN 1024
#define DIM_  1024
#define DI    2048
#define DS    16

// ===================== PTX helpers (family-target safe: no tcgen05) ============
__device__ __forceinline__ uint32_t smem_u32(const void* p) {
    uint32_t a;
    asm("{ .reg .u64 t; cvta.to.shared.u64 t, %1; cvt.u32.u64 %0, t; }" : "=r"(a) : "l"(p));
    return a;
}
#define CP_ASYNC16(dst, src) \
    asm volatile("cp.async.cg.shared.global [%0], [%1], 16;" :: "r"(dst), "l"(src))
#define CP_COMMIT() asm volatile("cp.async.commit_group;")
#define CP_WAIT1()  asm volatile("cp.async.wait_group 1;")
#define CP_WAIT0()  asm volatile("cp.async.wait_group 0;")

#define LDSM_X4(r0, r1, r2, r3, addr) \
    asm volatile("ldmatrix.sync.aligned.m8n8.x4.shared.b16 {%0,%1,%2,%3}, [%4];" \
                 : "=r"(r0), "=r"(r1), "=r"(r2), "=r"(r3) : "r"(addr))

#define MMA16816(c, a, b) \
    asm volatile("mma.sync.aligned.m16n8k16.row.col.f32.bf16.bf16.f32 " \
                 "{%0,%1,%2,%3},{%4,%5,%6,%7},{%8,%9},{%0,%1,%2,%3};" \
                 : "+f"((c)[0]), "+f"((c)[1]), "+f"((c)[2]), "+f"((c)[3]) \
                 : "r"((a)[0]), "r"((a)[1]), "r"((a)[2]), "r"((a)[3]), \
                   "r"((b)[0]), "r"((b)[1]))

static __device__ __forceinline__ uint32_t swz128(uint32_t off) {
    return off ^ ((off >> 3) & 0x70);
}

// ===================== scratch =====================
__device__ float g_xz[T_LEN * 4096];
__device__ float g_xc[T_LEN * DI];
__device__ float g_proj[T_LEN * 32];
__device__ float g_dt[T_LEN * DI];
__device__ float g_out0[T_LEN * DI];
__device__ float g_out1[(T_LEN / 2) * DI];
__device__ float g_out2[(T_LEN / 4) * DI];
__device__ float g_fused[T_LEN * DI];
__device__ float g_o[T_LEN * DIM_];
// bf16 hi/lo tripled operand buffers
__device__ __nv_bfloat16 g_x2[1024 * 3072];
__device__ __nv_bfloat16 g_wi2[4096 * 3072];
__device__ __nv_bfloat16 g_gw1b[1024 * 6144];
__device__ __nv_bfloat16 g_gw2b[2048 * 3072];
__device__ __nv_bfloat16 g_wob[1024 * 6144];
__device__ __nv_bfloat16 g_ctx2[1024 * 6144];
__device__ __nv_bfloat16 g_g1b[1024 * 3072];
__device__ __nv_bfloat16 g_u2[1024 * 6144];

// ===================== math helpers =====================
__device__ __forceinline__ float sigmoidf_(float x) { return 1.f / (1.f + __expf(-x)); }
__device__ __forceinline__ float siluf_(float x)    { return x * sigmoidf_(x); }
__device__ __forceinline__ float softplusf_(float x) {
    if (x > 20.f) return x;
    return log1pf(__expf(x));
}

// ===================== fp32 -> bf16 hi/lo triple converters =====================
// modeA: [hi | lo | hi], modeB: [hi | hi | lo]
__global__ void cvt_kernel(const float* __restrict__ src, __nv_bfloat16* __restrict__ dst,
                           int kshift, int modeA)
{
    int i = blockIdx.x * 256 + threadIdx.x;
    int K = 1 << kshift;
    int r = i >> kshift;
    int k = i & (K - 1);
    float v = src[i];
    __nv_bfloat16 hi = __float2bfloat16(v);
    __nv_bfloat16 lo = __float2bfloat16(v - __bfloat162float(hi));
    size_t base = (size_t)r * 3 * K;
    dst[base + k] = hi;
    dst[base + K + k] = modeA ? lo : hi;
    dst[base + 2 * K + k] = modeA ? hi : lo;
}

// ===================== HMMA bf16 GEMM =====================
// C[m,n] = sum_k A[m,k]*B[n,k]; A:[M,Kp] bf16, B:[N,Kp] bf16 (K-tripled hi/lo).
// 128x128 tile, BK=64, 8 warps (2x4), warp tile 64x32, double-buffered cp.async.
// mode 0: C[m*ldc+n] = acc
// mode 1: silu(acc) -> bf16 A-triple (Ktrip) into Cb
// mode 2: fused * sigmoid(acc) * silu(gate) -> bf16 A-triple into Cb
#define GSMEM_BYTES 66048   // max(tiles 65536, staging 128*129*4)

__device__ __forceinline__ void load_chunk(const __nv_bfloat16* gA, const __nv_bfloat16* gB,
                                           int Kp, int c, uint32_t smA, uint32_t smB, int tid)
{
    const __nv_bfloat16* a0 = gA + c * 64;
    const __nv_bfloat16* b0 = gB + c * 64;
#pragma unroll
    for (int s = 0; s < 4; s++) {
        int e = s * 256 + tid;
        int row = e >> 3, seg = e & 7;
        CP_ASYNC16(smA + swz128(row * 128 + seg * 16), a0 + (size_t)row * Kp + seg * 8);
    }
#pragma unroll
    for (int s = 0; s < 4; s++) {
        int e = s * 256 + tid;
        int row = e >> 3, seg = e & 7;
        CP_ASYNC16(smB + swz128(row * 128 + seg * 16), b0 + (size_t)row * Kp + seg * 8);
    }
}

__device__ __forceinline__ void store_pair_tripleA(__nv_bfloat16* rowp, int K, int col,
                                                   float a, float b)
{
    __nv_bfloat16 ha = __float2bfloat16(a), hb = __float2bfloat16(b);
    __nv_bfloat16 la = __float2bfloat16(a - __bfloat162float(ha));
    __nv_bfloat16 lb = __float2bfloat16(b - __bfloat162float(hb));
    __nv_bfloat162 h2; h2.x = ha; h2.y = hb;
    __nv_bfloat162 l2; l2.x = la; l2.y = lb;
    *reinterpret_cast<__nv_bfloat162*>(rowp + col) = h2;
    *reinterpret_cast<__nv_bfloat162*>(rowp + K + col) = l2;
    *reinterpret_cast<__nv_bfloat162*>(rowp + 2 * K + col) = h2;
}

__global__ void __launch_bounds__(256) gemm_bf16(
    const __nv_bfloat16* __restrict__ A,
    const __nv_bfloat16* __restrict__ B,
    int Kp,
    float* __restrict__ C, int ldc,
    __nv_bfloat16* __restrict__ Cb, int Ktrip,
    const float* __restrict__ fused, const float* __restrict__ xz,
    int mode)
{
    extern __shared__ char smem[];
    uint32_t sb = smem_u32(smem);
    const int tid = threadIdx.x, wid = tid >> 5, lane = tid & 31;
    const int wm = wid & 1, wn = wid >> 1;   // warp tile: rows wm*64, cols wn*32

    const int bm = blockIdx.y << 7, bn = blockIdx.x << 7;
    const __nv_bfloat16* gA = A + (size_t)bm * Kp;
    const __nv_bfloat16* gB = B + (size_t)bn * Kp;
    const int NC = Kp >> 6;

    const uint32_t aoff[2] = {sb, sb + 16384};
    const uint32_t boff[2] = {sb + 32768, sb + 49152};

    float acc[4][4][4];
#pragma unroll
    for (int mi = 0; mi < 4; mi++)
#pragma unroll
        for (int ni = 0; ni < 4; ni++)
#pragma unroll
            for (int q = 0; q < 4; q++) acc[mi][ni][q] = 0.f;

    // per-thread ldmatrix address components
    const int a_row = wm * 64 + (lane & 7) + ((lane >> 3) & 1) * 8;  // + mi*16
    const int a_kh  = lane >> 4;                                      // kseg half
    const int b_row = wn * 32 + (lane & 7) + (lane >> 4) * 8;         // + nhalf*16
    const int b_kh  = (lane >> 3) & 1;

    load_chunk(gA, gB, Kp, 0, aoff[0], boff[0], tid);
    CP_COMMIT();

    for (int c = 0; c < NC; c++) {
        if (c + 1 < NC) {
            load_chunk(gA, gB, Kp, c + 1, aoff[(c + 1) & 1], boff[(c + 1) & 1], tid);
            CP_COMMIT();
            CP_WAIT1();
        } else {
            CP_WAIT0();
        }
        __syncthreads();

        const uint32_t ab = aoff[c & 1], bb = boff[c & 1];
#pragma unroll
        for (int ks = 0; ks < 4; ks++) {
            uint32_t aF[4][4];
#pragma unroll
            for (int mi = 0; mi < 4; mi++) {
                uint32_t ad = ab + swz128((uint32_t)(a_row + mi * 16) * 128 +
                                          (uint32_t)(ks * 2 + a_kh) * 16);
                LDSM_X4(aF[mi][0], aF[mi][1], aF[mi][2], aF[mi][3], ad);
            }
            uint32_t bF[4][2];
#pragma unroll
            for (int nh = 0; nh < 2; nh++) {
                uint32_t r0, r1, r2, r3;
                uint32_t bd = bb + swz128((uint32_t)(b_row + nh * 16) * 128 +
                                          (uint32_t)(ks * 2 + b_kh) * 16);
                LDSM_X4(r0, r1, r2, r3, bd);
                bF[nh * 2][0] = r0; bF[nh * 2][1] = r1;
                bF[nh * 2 + 1][0] = r2; bF[nh * 2 + 1][1] = r3;
            }
#pragma unroll
            for (int mi = 0; mi < 4; mi++)
#pragma unroll
                for (int ni = 0; ni < 4; ni++)
                    MMA16816(acc[mi][ni], aF[mi], bF[ni]);
        }
        __syncthreads();
    }

    // stage accumulators through SMEM (stride 129 -> conflict-light)
    float* cs = (float*)smem;
#pragma unroll
    for (int mi = 0; mi < 4; mi++) {
        int r0 = wm * 64 + mi * 16 + (lane >> 2);
#pragma unroll
        for (int ni = 0; ni < 4; ni++) {
            int col = wn * 32 + ni * 8 + (lane & 3) * 2;
            cs[r0 * 129 + col]           = acc[mi][ni][0];
            cs[r0 * 129 + col + 1]       = acc[mi][ni][1];
            cs[(r0 + 8) * 129 + col]     = acc[mi][ni][2];
            cs[(r0 + 8) * 129 + col + 1] = acc[mi][ni][3];
        }
    }
    __syncthreads();

    const int row = tid >> 1, half = tid & 1;
    const int m = bm + row;
    const float* crow = cs + row * 129 + half * 64;
    if (mode == 0) {
        float* orow = C + (size_t)m * ldc + bn + half * 64;
#pragma unroll 4
        for (int kk = 0; kk < 16; kk++) {
            float4 v = make_float4(crow[kk * 4], crow[kk * 4 + 1],
                                   crow[kk * 4 + 2], crow[kk * 4 + 3]);
            *reinterpret_cast<float4*>(orow + kk * 4) = v;
        }
    } else if (mode == 1) {
        __nv_bfloat16* orow = Cb + (size_t)m * 3 * Ktrip + bn + half * 64;
#pragma unroll 4
        for (int kk = 0; kk < 32; kk++) {
            float a = siluf_(crow[kk * 2]);
            float b = siluf_(crow[kk * 2 + 1]);
            store_pair_tripleA(orow, Ktrip, kk * 2, a, b);
        }
    } else if (mode == 2) {
        __nv_bfloat16* orow = Cb + (size_t)m * 3 * Ktrip + bn + half * 64;
        const float* frow = fused + (size_t)m * 2048 + bn + half * 64;
        const float* grow = xz + (size_t)m * 4096 + 2048 + bn + half * 64;
#pragma unroll 4
        for (int kk = 0; kk < 32; kk++) {
            float a = frow[kk * 2]     * sigmoidf_(crow[kk * 2])     * siluf_(grow[kk * 2]);
            float b = frow[kk * 2 + 1] * sigmoidf_(crow[kk * 2 + 1]) * siluf_(grow[kk * 2 + 1]);
            store_pair_tripleA(orow, Ktrip, kk * 2, a, b);
        }
    }
}

// ===================== non-GEMM kernels =====================
__global__ void conv_silu_kernel(const float* __restrict__ xz,
                                 const float* __restrict__ cw,
                                 const float* __restrict__ cb,
                                 float* __restrict__ xc,
                                 int T, int stride)
{
    int idx = blockIdx.x * blockDim.x + threadIdx.x;
    if (idx >= T * DI) return;
    int t = idx >> 11;
    int d = idx & (DI - 1);
    float4 w4 = *reinterpret_cast<const float4*>(cw + d * 4);
    float wk[4] = {w4.x, w4.y, w4.z, w4.w};
    float acc = cb[d];
    float inv = 1.f / (float)stride;
#pragma unroll
    for (int k = 0; k < 4; k++) {
        int tt = t - 3 + k;
        if (tt >= 0) {
            float v = 0.f;
            int base = tt * stride;
            for (int r = 0; r < stride; r++) v += xz[(size_t)(base + r) * 4096 + d];
            acc += wk[k] * (v * inv);
        }
    }
    xc[idx] = siluf_(acc);
}

__global__ void xproj_kernel(const float* __restrict__ xc,
                             const float* __restrict__ W,
                             float* __restrict__ proj)
{
    int t = blockIdx.x;
    __shared__ float sx[DI];
    for (int i = threadIdx.x; i < DI; i += 256) sx[i] = xc[(size_t)t * DI + i];
    __syncthreads();
    int warp = threadIdx.x >> 5, lane = threadIdx.x & 31;
    for (int j = warp; j < 32; j += 8) {
        const float* w = W + (size_t)j * DI;
        float s = 0.f;
        for (int i = lane * 4; i < DI; i += 128) {
            float4 a = *reinterpret_cast<const float4*>(&sx[i]);
            float4 b = *reinterpret_cast<const float4*>(&w[i]);
            s += a.x * b.x + a.y * b.y + a.z * b.z + a.w * b.w;
        }
        for (int off = 16; off; off >>= 1) s += __shfl_xor_sync(0xffffffffu, s, off);
        if (!lane) proj[t * 32 + j] = s;
    }
}

__global__ void dtproj_kernel(const float* __restrict__ proj,
                              const float* __restrict__ dtw,
                              const float* __restrict__ dtb,
                              float* __restrict__ dt, int T)
{
    int idx = blockIdx.x * blockDim.x + threadIdx.x;
    if (idx >= T * DI) return;
    int t = idx >> 11;
    int d = idx & (DI - 1);
    const float* bp = proj + t * 32;
    const float4* w4 = reinterpret_cast<const float4*>(dtw + (size_t)d * 16);
    float s = dtb[d];
#pragma unroll
    for (int q = 0; q < 4; q++) {
        float4 w = w4[q];
        s += bp[q * 4 + 0] * w.x + bp[q * 4 + 1] * w.y +
             bp[q * 4 + 2] * w.z + bp[q * 4 + 3] * w.w;
    }
    dt[idx] = softplusf_(softplusf_(s));
}

__global__ void scan_kernel(const float* __restrict__ dt,
                            const float* __restrict__ proj,
                            const float* __restrict__ xc,
                            const float* __restrict__ Dp,
                            float* __restrict__ y, int T)
{
    int gid = blockIdx.x * blockDim.x + threadIdx.x;
    int n = gid & 15;
    int d = gid >> 4;
    float An = -(float)(n + 1);
    float Dpd = Dp[d];
    float h = 0.f;
    for (int t = 0; t < T; t++) {
        float dtv = dt[(size_t)t * DI + d];
        float xcv = xc[(size_t)t * DI + d];
        float Bv  = proj[t * 32 + n];
        float Cv  = proj[t * 32 + 16 + n];
        float dA  = fmaxf(__expf(dtv * An), 1e-38f);
        float dBx = fmaxf(dtv * Bv * xcv, 1e-38f);
        h = dA * h + dBx;
        float v = Cv * h;
        v += __shfl_xor_sync(0xffffffffu, v, 8);
        v += __shfl_xor_sync(0xffffffffu, v, 4);
        v += __shfl_xor_sync(0xffffffffu, v, 2);
        v += __shfl_xor_sync(0xffffffffu, v, 1);
        if (n == 0) y[(size_t)t * DI + d] = v + Dpd * xcv;
    }
}

__device__ __forceinline__ float upsample_read(const float* __restrict__ y,
                                               int Tin, int t, int d)
{
    if (Tin == T_LEN) return y[(size_t)t * DI + d];
    float scale = (float)Tin / (float)T_LEN;
    float pos = ((float)t + 0.5f) * scale - 0.5f;
    pos = fminf(fmaxf(pos, 0.f), (float)(Tin - 1));
    int lo = (int)floorf(pos);
    int hi = min(lo + 1, Tin - 1);
    float w = pos - (float)lo;
    return y[(size_t)lo * DI + d] * (1.f - w) + y[(size_t)hi * DI + d] * w;
}

__global__ void fuse_kernel(const float* __restrict__ y0,
                            const float* __restrict__ y1,
                            const float* __restrict__ y2,
                            const float* __restrict__ sw,
                            float* __restrict__ fused,
                            __nv_bfloat16* __restrict__ ctx2)
{
    int idx = blockIdx.x * blockDim.x + threadIdx.x;
    if (idx >= T_LEN * DI) return;
    int t = idx >> 11, d = idx & (DI - 1);
    float w0 = sw[0], w1 = sw[1], w2 = sw[2];
    float m = fmaxf(w0, fmaxf(w1, w2));
    float e0 = __expf(w0 - m), e1 = __expf(w1 - m), e2 = __expf(w2 - m);
    float inv = 1.f / (e0 + e1 + e2);
    float u0 = y0[idx];
    float u1 = upsample_read(y1, T_LEN / 2, t, d);
    float u2 = upsample_read(y2, T_LEN / 4, t, d);
    fused[idx] = (e0 * u0 + e1 * u1 + e2 * u2) * inv;
    float v = (u0 + u1 + u2) * (1.f / 3.f);
    __nv_bfloat16 hi = __float2bfloat16(v);
    __nv_bfloat16 lo = __float2bfloat16(v - __bfloat162float(hi));
    size_t base = (size_t)t * 6144;
    ctx2[base + d] = hi;
    ctx2[base + 2048 + d] = lo;
    ctx2[base + 4096 + d] = hi;
}

__global__ void ln_kernel(const float* __restrict__ o,
                          const float* __restrict__ x,
                          const float* __restrict__ g,
                          const float* __restrict__ bb,
                          float* __restrict__ out)
{
    int t = blockIdx.x;
    int tid = threadIdx.x;
    float v[4];
    float s = 0.f, s2 = 0.f;
#pragma unroll
    for (int i = 0; i < 4; i++) {
        int j = tid + i * 256;
        float y = o[(size_t)t * DIM_ + j] + x[(size_t)t * DIM_ + j];
        v[i] = y; s += y; s2 += y * y;
    }
    __shared__ float sh1[8], sh2[8];
    for (int off = 16; off; off >>= 1) {
        s  += __shfl_xor_sync(0xffffffffu, s, off);
        s2 += __shfl_xor_sync(0xffffffffu, s2, off);
    }
    int w = tid >> 5, l = tid & 31;
    if (!l) { sh1[w] = s; sh2[w] = s2; }
    __syncthreads();
    if (w == 0) {
        s  = (l < 8) ? sh1[l] : 0.f;
        s2 = (l < 8) ? sh2[l] : 0.f;
        for (int off = 4; off; off >>= 1) {
            s  += __shfl_xor_sync(0xffffffffu, s, off);
            s2 += __shfl_xor_sync(0xffffffffu, s2, off);
        }
        if (!l) { sh1[0] = s; sh2[0] = s2; }
    }
    __syncthreads();
    float mu  = sh1[0] * (1.f / DIM_);
    float var = sh2[0] * (1.f / DIM_) - mu * mu;
    float inv = rsqrtf(var + 1e-5f);
#pragma unroll
    for (int i = 0; i < 4; i++) {
        int j = tid + i * 256;
        out[(size_t)t * DIM_ + j] = (v[i] - mu) * inv * g[j] + bb[j];
    }
}

// ===================== launch =====================
extern "C" void kernel_launch(void* const* d_in, const int* in_sizes, int n_in,
                              void* d_out, int out_size)
{
    const float* x        = (const float*)d_in[0];
    const float* in_proj  = (const float*)d_in[1];
    const float* conv_w   = (const float*)d_in[2];
    const float* conv_b   = (const float*)d_in[3];
    const float* xproj_w  = (const float*)d_in[4];
    const float* dtproj_w = (const float*)d_in[5];
    const float* dtproj_b = (const float*)d_in[6];
    const float* D_param  = (const float*)d_in[7];
    const float* sw       = (const float*)d_in[8];
    const float* gate_w1  = (const float*)d_in[9];
    const float* gate_w2  = (const float*)d_in[10];
    const float* out_proj = (const float*)d_in[11];
    const float* ln_g     = (const float*)d_in[12];
    const float* ln_b     = (const float*)d_in[13];
    float* out = (float*)d_out;

    float *xz, *xc, *proj, *dt, *o0, *o1, *o2, *fused, *o;
    __nv_bfloat16 *x2, *wi2, *gw1b, *gw2b, *wob, *ctx2, *g1b, *u2;
    cudaGetSymbolAddress((void**)&xz,    g_xz);
    cudaGetSymbolAddress((void**)&xc,    g_xc);
    cudaGetSymbolAddress((void**)&proj,  g_proj);
    cudaGetSymbolAddress((void**)&dt,    g_dt);
    cudaGetSymbolAddress((void**)&o0,    g_out0);
    cudaGetSymbolAddress((void**)&o1,    g_out1);
    cudaGetSymbolAddress((void**)&o2,    g_out2);
    cudaGetSymbolAddress((void**)&fused, g_fused);
    cudaGetSymbolAddress((void**)&o,     g_o);
    cudaGetSymbolAddress((void**)&x2,    g_x2);
    cudaGetSymbolAddress((void**)&wi2,   g_wi2);
    cudaGetSymbolAddress((void**)&gw1b,  g_gw1b);
    cudaGetSymbolAddress((void**)&gw2b,  g_gw2b);
    cudaGetSymbolAddress((void**)&wob,   g_wob);
    cudaGetSymbolAddress((void**)&ctx2,  g_ctx2);
    cudaGetSymbolAddress((void**)&g1b,   g_g1b);
    cudaGetSymbolAddress((void**)&u2,    g_u2);

    cudaFuncSetAttribute(gemm_bf16, cudaFuncAttributeMaxDynamicSharedMemorySize, GSMEM_BYTES);

    // hi/lo conversions: x (A-mode), weights (B-mode)
    cvt_kernel<<<(1024 * 1024) / 256, 256>>>(x,        x2,   10, 1);
    cvt_kernel<<<(4096 * 1024) / 256, 256>>>(in_proj,  wi2,  10, 0);
    cvt_kernel<<<(1024 * 2048) / 256, 256>>>(gate_w1,  gw1b, 11, 0);
    cvt_kernel<<<(2048 * 1024) / 256, 256>>>(gate_w2,  gw2b, 10, 0);
    cvt_kernel<<<(1024 * 2048) / 256, 256>>>(out_proj, wob,  11, 0);

    // in_proj: xz[1024,4096] = x @ in_proj_w.T
    gemm_bf16<<<dim3(32, 8), 256, GSMEM_BYTES>>>(x2, wi2, 3072, xz, 4096,
                                                 nullptr, 0, nullptr, nullptr, 0);

    float* outs[3] = {o0, o1, o2};
    for (int s = 0; s < 3; s++) {
        int T = T_LEN >> s;
        int stride = 1 << s;
        conv_silu_kernel<<<(T * DI) / 256, 256>>>(xz, conv_w + s * DI * 4, conv_b + s * DI, xc, T, stride);
        xproj_kernel<<<T, 256>>>(xc, xproj_w + s * 32 * DI, proj);
        dtproj_kernel<<<(T * DI) / 256, 256>>>(proj, dtproj_w + s * DI * DS, dtproj_b + s * DI, dt, T);
        scan_kernel<<<(DI * DS) / 256, 256>>>(dt, proj, xc, D_param + s * DI, outs[s], T);
    }

    fuse_kernel<<<(T_LEN * DI) / 256, 256>>>(o0, o1, o2, sw, fused, ctx2);

    // gate1: g1 = silu(ctx @ gate_w1.T)  -> bf16 triple (K=1024)
    gemm_bf16<<<dim3(8, 8), 256, GSMEM_BYTES>>>(ctx2, gw1b, 6144, nullptr, 0,
                                                g1b, 1024, nullptr, nullptr, 1);
    // gate2: u = fused * sigmoid(g1 @ gate_w2.T) * silu(gate) -> bf16 triple (K=2048)
    gemm_bf16<<<dim3(16, 8), 256, GSMEM_BYTES>>>(g1b, gw2b, 3072, nullptr, 0,
                                                 u2, 2048, fused, xz, 2);
    // out_proj: o = u @ out_proj_w.T
    gemm_bf16<<<dim3(8, 8), 256, GSMEM_BYTES>>>(u2, wob, 6144, o, 1024,
                                                nullptr, 0, nullptr, nullptr, 0);

    ln_kernel<<<T_LEN, 256>>>(o, x, ln_g, ln_b, out);
}

// round 8
// speedup vs baseline: 1.8268x; 1.2833x over previous
#include <cuda_runtime.h>
#include <cuda_bf16.h>
#include <cstdint>
#include <math.h>

#define T_LEN 1024
#define DIM_  1024
#define DI    2048
#define DS    16

// ===================== PTX helpers (family-target safe: no tcgen05) ============
__device__ __forceinline__ uint32_t smem_u32(const void* p) {
    uint32_t a;
    asm("{ .reg .u64 t; cvta.to.shared.u64 t, %1; cvt.u32.u64 %0, t; }" : "=r"(a) : "l"(p));
    return a;
}
#define CP_ASYNC16(dst, src) \
    asm volatile("cp.async.cg.shared.global [%0], [%1], 16;" :: "r"(dst), "l"(src))
#define CP_COMMIT() asm volatile("cp.async.commit_group;")
#define CP_WAIT1()  asm volatile("cp.async.wait_group 1;")
#define CP_WAIT0()  asm volatile("cp.async.wait_group 0;")

#define LDSM_X4(r0, r1, r2, r3, addr) \
    asm volatile("ldmatrix.sync.aligned.m8n8.x4.shared.b16 {%0,%1,%2,%3}, [%4];" \
                 : "=r"(r0), "=r"(r1), "=r"(r2), "=r"(r3) : "r"(addr))

#define MMA16816(c, a, b) \
    asm volatile("mma.sync.aligned.m16n8k16.row.col.f32.bf16.bf16.f32 " \
                 "{%0,%1,%2,%3},{%4,%5,%6,%7},{%8,%9},{%0,%1,%2,%3};" \
                 : "+f"((c)[0]), "+f"((c)[1]), "+f"((c)[2]), "+f"((c)[3]) \
                 : "r"((a)[0]), "r"((a)[1]), "r"((a)[2]), "r"((a)[3]), \
                   "r"((b)[0]), "r"((b)[1]))

static __device__ __forceinline__ uint32_t swz128(uint32_t off) {
    return off ^ ((off >> 3) & 0x70);
}

// ===================== scratch =====================
__device__ float g_xz[T_LEN * 4096];
__device__ float g_xc[T_LEN * DI];
__device__ float g_proj[T_LEN * 32];
__device__ float g_dt[T_LEN * DI];
__device__ float g_out0[T_LEN * DI];
__device__ float g_out1[(T_LEN / 2) * DI];
__device__ float g_out2[(T_LEN / 4) * DI];
__device__ float g_fused[T_LEN * DI];
__device__ float g_scr[2 * T_LEN * DIM_];   // split-K fp32 partials
// bf16 hi/lo tripled operand buffers
__device__ __nv_bfloat16 g_x2[1024 * 3072];
__device__ __nv_bfloat16 g_wi2[4096 * 3072];
__device__ __nv_bfloat16 g_gw1b[1024 * 6144];
__device__ __nv_bfloat16 g_gw2b[2048 * 3072];
__device__ __nv_bfloat16 g_wob[1024 * 6144];
__device__ __nv_bfloat16 g_ctx2[1024 * 6144];
__device__ __nv_bfloat16 g_g1b[1024 * 3072];
__device__ __nv_bfloat16 g_u2[1024 * 6144];

// ===================== math helpers =====================
__device__ __forceinline__ float sigmoidf_(float x) { return 1.f / (1.f + __expf(-x)); }
__device__ __forceinline__ float siluf_(float x)    { return x * sigmoidf_(x); }
__device__ __forceinline__ float softplusf_(float x) {
    if (x > 20.f) return x;
    return log1pf(__expf(x));
}

// ===================== fp32 -> bf16 hi/lo triple converters =====================
// modeA: [hi | lo | hi], modeB: [hi | hi | lo]
__global__ void cvt_kernel(const float* __restrict__ src, __nv_bfloat16* __restrict__ dst,
                           int kshift, int modeA)
{
    int i = blockIdx.x * 256 + threadIdx.x;
    int K = 1 << kshift;
    int r = i >> kshift;
    int k = i & (K - 1);
    float v = src[i];
    __nv_bfloat16 hi = __float2bfloat16(v);
    __nv_bfloat16 lo = __float2bfloat16(v - __bfloat162float(hi));
    size_t base = (size_t)r * 3 * K;
    dst[base + k] = hi;
    dst[base + K + k] = modeA ? lo : hi;
    dst[base + 2 * K + k] = modeA ? hi : lo;
}

// ===================== HMMA bf16 GEMM =====================
// C[m,n] = sum_k A[m,k]*B[n,k]; A:[M,Kstride] bf16, B:[N,Kstride] (K-tripled hi/lo).
// 128x128 tile, BK=64, 8 warps (2x4), warp tile 64x32, double-buffered cp.async.
// blockIdx.z slices K: A/B advance z*Kp, C advances z*czstride.
// mode 0: C[m*ldc+n] = acc  (fp32; used for full or split-K partial)
// mode 2: fused * sigmoid(acc) * silu(gate) -> bf16 A-triple into Cb
#define GSMEM_BYTES 66048

__device__ __forceinline__ void load_chunk(const __nv_bfloat16* gA, const __nv_bfloat16* gB,
                                           int Kstride, int c, uint32_t smA, uint32_t smB,
                                           int tid)
{
    const __nv_bfloat16* a0 = gA + c * 64;
    const __nv_bfloat16* b0 = gB + c * 64;
#pragma unroll
    for (int s = 0; s < 4; s++) {
        int e = s * 256 + tid;
        int row = e >> 3, seg = e & 7;
        CP_ASYNC16(smA + swz128(row * 128 + seg * 16), a0 + (size_t)row * Kstride + seg * 8);
    }
#pragma unroll
    for (int s = 0; s < 4; s++) {
        int e = s * 256 + tid;
        int row = e >> 3, seg = e & 7;
        CP_ASYNC16(smB + swz128(row * 128 + seg * 16), b0 + (size_t)row * Kstride + seg * 8);
    }
}

__device__ __forceinline__ void store_pair_tripleA(__nv_bfloat16* rowp, int K, int col,
                                                   float a, float b)
{
    __nv_bfloat16 ha = __float2bfloat16(a), hb = __float2bfloat16(b);
    __nv_bfloat16 la = __float2bfloat16(a - __bfloat162float(ha));
    __nv_bfloat16 lb = __float2bfloat16(b - __bfloat162float(hb));
    __nv_bfloat162 h2; h2.x = ha; h2.y = hb;
    __nv_bfloat162 l2; l2.x = la; l2.y = lb;
    *reinterpret_cast<__nv_bfloat162*>(rowp + col) = h2;
    *reinterpret_cast<__nv_bfloat162*>(rowp + K + col) = l2;
    *reinterpret_cast<__nv_bfloat162*>(rowp + 2 * K + col) = h2;
}

__global__ void __launch_bounds__(256) gemm_bf16(
    const __nv_bfloat16* __restrict__ A,
    const __nv_bfloat16* __restrict__ B,
    int Kp, int Kstride,
    float* __restrict__ C, int ldc, size_t czstride,
    __nv_bfloat16* __restrict__ Cb, int Ktrip,
    const float* __restrict__ fused, const float* __restrict__ xz,
    int mode)
{
    extern __shared__ char smem[];
    uint32_t sb = smem_u32(smem);
    const int tid = threadIdx.x, wid = tid >> 5, lane = tid & 31;
    const int wm = wid & 1, wn = wid >> 1;

    const int bm = blockIdx.y << 7, bn = blockIdx.x << 7;
    const int kz = blockIdx.z;
    const __nv_bfloat16* gA = A + (size_t)bm * Kstride + (size_t)kz * Kp;
    const __nv_bfloat16* gB = B + (size_t)bn * Kstride + (size_t)kz * Kp;
    C += (size_t)kz * czstride;
    const int NC = Kp >> 6;

    const uint32_t aoff[2] = {sb, sb + 16384};
    const uint32_t boff[2] = {sb + 32768, sb + 49152};

    float acc[4][4][4];
#pragma unroll
    for (int mi = 0; mi < 4; mi++)
#pragma unroll
        for (int ni = 0; ni < 4; ni++)
#pragma unroll
            for (int q = 0; q < 4; q++) acc[mi][ni][q] = 0.f;

    const int a_row = wm * 64 + (lane & 7) + ((lane >> 3) & 1) * 8;
    const int a_kh  = lane >> 4;
    const int b_row = wn * 32 + (lane & 7) + (lane >> 4) * 8;
    const int b_kh  = (lane >> 3) & 1;

    load_chunk(gA, gB, Kstride, 0, aoff[0], boff[0], tid);
    CP_COMMIT();

    for (int c = 0; c < NC; c++) {
        if (c + 1 < NC) {
            load_chunk(gA, gB, Kstride, c + 1, aoff[(c + 1) & 1], boff[(c + 1) & 1], tid);
            CP_COMMIT();
            CP_WAIT1();
        } else {
            CP_WAIT0();
        }
        __syncthreads();

        const uint32_t ab = aoff[c & 1], bb = boff[c & 1];
#pragma unroll
        for (int ks = 0; ks < 4; ks++) {
            uint32_t aF[4][4];
#pragma unroll
            for (int mi = 0; mi < 4; mi++) {
                uint32_t ad = ab + swz128((uint32_t)(a_row + mi * 16) * 128 +
                                          (uint32_t)(ks * 2 + a_kh) * 16);
                LDSM_X4(aF[mi][0], aF[mi][1], aF[mi][2], aF[mi][3], ad);
            }
            uint32_t bF[4][2];
#pragma unroll
            for (int nh = 0; nh < 2; nh++) {
                uint32_t r0, r1, r2, r3;
                uint32_t bd = bb + swz128((uint32_t)(b_row + nh * 16) * 128 +
                                          (uint32_t)(ks * 2 + b_kh) * 16);
                LDSM_X4(r0, r1, r2, r3, bd);
                bF[nh * 2][0] = r0; bF[nh * 2][1] = r1;
                bF[nh * 2 + 1][0] = r2; bF[nh * 2 + 1][1] = r3;
            }
#pragma unroll
            for (int mi = 0; mi < 4; mi++)
#pragma unroll
                for (int ni = 0; ni < 4; ni++)
                    MMA16816(acc[mi][ni], aF[mi], bF[ni]);
        }
        __syncthreads();
    }

    // stage accumulators through SMEM
    float* cs = (float*)smem;
#pragma unroll
    for (int mi = 0; mi < 4; mi++) {
        int r0 = wm * 64 + mi * 16 + (lane >> 2);
#pragma unroll
        for (int ni = 0; ni < 4; ni++) {
            int col = wn * 32 + ni * 8 + (lane & 3) * 2;
            cs[r0 * 129 + col]           = acc[mi][ni][0];
            cs[r0 * 129 + col + 1]       = acc[mi][ni][1];
            cs[(r0 + 8) * 129 + col]     = acc[mi][ni][2];
            cs[(r0 + 8) * 129 + col + 1] = acc[mi][ni][3];
        }
    }
    __syncthreads();

    const int row = tid >> 1, half = tid & 1;
    const int m = bm + row;
    const float* crow = cs + row * 129 + half * 64;
    if (mode == 0) {
        float* orow = C + (size_t)m * ldc + bn + half * 64;
#pragma unroll 4
        for (int kk = 0; kk < 16; kk++) {
            float4 v = make_float4(crow[kk * 4], crow[kk * 4 + 1],
                                   crow[kk * 4 + 2], crow[kk * 4 + 3]);
            *reinterpret_cast<float4*>(orow + kk * 4) = v;
        }
    } else {
        __nv_bfloat16* orow = Cb + (size_t)m * 3 * Ktrip + bn + half * 64;
        const float* frow = fused + (size_t)m * 2048 + bn + half * 64;
        const float* grow = xz + (size_t)m * 4096 + 2048 + bn + half * 64;
#pragma unroll 4
        for (int kk = 0; kk < 32; kk++) {
            float a = frow[kk * 2]     * sigmoidf_(crow[kk * 2])     * siluf_(grow[kk * 2]);
            float b = frow[kk * 2 + 1] * sigmoidf_(crow[kk * 2 + 1]) * siluf_(grow[kk * 2 + 1]);
            store_pair_tripleA(orow, Ktrip, kk * 2, a, b);
        }
    }
}

// ===================== split-K combiners =====================
// g1 = silu(p0 + p1) -> bf16 A-triple rows of length 3*1024 into g1b
__global__ void comb_silu_triple(const float* __restrict__ p0,
                                 const float* __restrict__ p1,
                                 __nv_bfloat16* __restrict__ g1b)
{
    int i = blockIdx.x * 256 + threadIdx.x;
    if (i >= T_LEN * DIM_) return;
    int m = i >> 10, k = i & 1023;
    float v = siluf_(p0[i] + p1[i]);
    __nv_bfloat16 hi = __float2bfloat16(v);
    __nv_bfloat16 lo = __float2bfloat16(v - __bfloat162float(hi));
    __nv_bfloat16* rowp = g1b + (size_t)m * 3072;
    rowp[k] = hi;
    rowp[1024 + k] = lo;
    rowp[2048 + k] = hi;
}

// ===================== non-GEMM kernels =====================
__global__ void conv_silu_kernel(const float* __restrict__ xz,
                                 const float* __restrict__ cw,
                                 const float* __restrict__ cb,
                                 float* __restrict__ xc,
                                 int T, int stride)
{
    int idx = blockIdx.x * blockDim.x + threadIdx.x;
    if (idx >= T * DI) return;
    int t = idx >> 11;
    int d = idx & (DI - 1);
    float4 w4 = *reinterpret_cast<const float4*>(cw + d * 4);
    float wk[4] = {w4.x, w4.y, w4.z, w4.w};
    float acc = cb[d];
    float inv = 1.f / (float)stride;
#pragma unroll
    for (int k = 0; k < 4; k++) {
        int tt = t - 3 + k;
        if (tt >= 0) {
            float v = 0.f;
            int base = tt * stride;
            for (int r = 0; r < stride; r++) v += xz[(size_t)(base + r) * 4096 + d];
            acc += wk[k] * (v * inv);
        }
    }
    xc[idx] = siluf_(acc);
}

__global__ void xproj_kernel(const float* __restrict__ xc,
                             const float* __restrict__ W,
                             float* __restrict__ proj)
{
    int t = blockIdx.x;
    __shared__ float sx[DI];
    for (int i = threadIdx.x; i < DI; i += 256) sx[i] = xc[(size_t)t * DI + i];
    __syncthreads();
    int warp = threadIdx.x >> 5, lane = threadIdx.x & 31;
    for (int j = warp; j < 32; j += 8) {
        const float* w = W + (size_t)j * DI;
        float s = 0.f;
        for (int i = lane * 4; i < DI; i += 128) {
            float4 a = *reinterpret_cast<const float4*>(&sx[i]);
            float4 b = *reinterpret_cast<const float4*>(&w[i]);
            s += a.x * b.x + a.y * b.y + a.z * b.z + a.w * b.w;
        }
        for (int off = 16; off; off >>= 1) s += __shfl_xor_sync(0xffffffffu, s, off);
        if (!lane) proj[t * 32 + j] = s;
    }
}

__global__ void dtproj_kernel(const float* __restrict__ proj,
                              const float* __restrict__ dtw,
                              const float* __restrict__ dtb,
                              float* __restrict__ dt, int T)
{
    int idx = blockIdx.x * blockDim.x + threadIdx.x;
    if (idx >= T * DI) return;
    int t = idx >> 11;
    int d = idx & (DI - 1);
    const float* bp = proj + t * 32;
    const float4* w4 = reinterpret_cast<const float4*>(dtw + (size_t)d * 16);
    float s = dtb[d];
#pragma unroll
    for (int q = 0; q < 4; q++) {
        float4 w = w4[q];
        s += bp[q * 4 + 0] * w.x + bp[q * 4 + 1] * w.y +
             bp[q * 4 + 2] * w.z + bp[q * 4 + 3] * w.w;
    }
    dt[idx] = softplusf_(softplusf_(s));
}

// scan: unrolled x4 — 4 independent butterfly chains amortize SHFL latency
__global__ void scan_kernel(const float* __restrict__ dt,
                            const float* __restrict__ proj,
                            const float* __restrict__ xc,
                            const float* __restrict__ Dp,
                            float* __restrict__ y, int T)
{
    int gid = blockIdx.x * blockDim.x + threadIdx.x;
    int n = gid & 15;
    int d = gid >> 4;
    float An = -(float)(n + 1);
    float Dpd = Dp[d];
    float h = 0.f;
    for (int t = 0; t < T; t += 4) {
        float v[4], xcs[4];
#pragma unroll
        for (int q = 0; q < 4; q++) {
            int tt = t + q;
            float dtv = dt[(size_t)tt * DI + d];
            float xcv = xc[(size_t)tt * DI + d];
            float Bv  = proj[tt * 32 + n];
            float Cv  = proj[tt * 32 + 16 + n];
            float dA  = fmaxf(__expf(dtv * An), 1e-38f);
            float dBx = fmaxf(dtv * Bv * xcv, 1e-38f);
            h = dA * h + dBx;
            v[q] = Cv * h;
            xcs[q] = xcv;
        }
#pragma unroll
        for (int off = 8; off; off >>= 1) {
#pragma unroll
            for (int q = 0; q < 4; q++)
                v[q] += __shfl_xor_sync(0xffffffffu, v[q], off);
        }
        if (n == 0) {
#pragma unroll
            for (int q = 0; q < 4; q++)
                y[(size_t)(t + q) * DI + d] = v[q] + Dpd * xcs[q];
        }
    }
}

__device__ __forceinline__ float upsample_read(const float* __restrict__ y,
                                               int Tin, int t, int d)
{
    if (Tin == T_LEN) return y[(size_t)t * DI + d];
    float scale = (float)Tin / (float)T_LEN;
    float pos = ((float)t + 0.5f) * scale - 0.5f;
    pos = fminf(fmaxf(pos, 0.f), (float)(Tin - 1));
    int lo = (int)floorf(pos);
    int hi = min(lo + 1, Tin - 1);
    float w = pos - (float)lo;
    return y[(size_t)lo * DI + d] * (1.f - w) + y[(size_t)hi * DI + d] * w;
}

__global__ void fuse_kernel(const float* __restrict__ y0,
                            const float* __restrict__ y1,
                            const float* __restrict__ y2,
                            const float* __restrict__ sw,
                            float* __restrict__ fused,
                            __nv_bfloat16* __restrict__ ctx2)
{
    int idx = blockIdx.x * blockDim.x + threadIdx.x;
    if (idx >= T_LEN * DI) return;
    int t = idx >> 11, d = idx & (DI - 1);
    float w0 = sw[0], w1 = sw[1], w2 = sw[2];
    float m = fmaxf(w0, fmaxf(w1, w2));
    float e0 = __expf(w0 - m), e1 = __expf(w1 - m), e2 = __expf(w2 - m);
    float inv = 1.f / (e0 + e1 + e2);
    float u0 = y0[idx];
    float u1 = upsample_read(y1, T_LEN / 2, t, d);
    float u2 = upsample_read(y2, T_LEN / 4, t, d);
    fused[idx] = (e0 * u0 + e1 * u1 + e2 * u2) * inv;
    float v = (u0 + u1 + u2) * (1.f / 3.f);
    __nv_bfloat16 hi = __float2bfloat16(v);
    __nv_bfloat16 lo = __float2bfloat16(v - __bfloat162float(hi));
    size_t base = (size_t)t * 6144;
    ctx2[base + d] = hi;
    ctx2[base + 2048 + d] = lo;
    ctx2[base + 4096 + d] = hi;
}

// residual + LayerNorm, fused with out_proj split-K combine: y = p0 + p1 + x
__global__ void ln_kernel(const float* __restrict__ p0,
                          const float* __restrict__ p1,
                          const float* __restrict__ x,
                          const float* __restrict__ g,
                          const float* __restrict__ bb,
                          float* __restrict__ out)
{
    int t = blockIdx.x;
    int tid = threadIdx.x;
    float v[4];
    float s = 0.f, s2 = 0.f;
#pragma unroll
    for (int i = 0; i < 4; i++) {
        int j = tid + i * 256;
        size_t off = (size_t)t * DIM_ + j;
        float y = p0[off] + p1[off] + x[off];
        v[i] = y; s += y; s2 += y * y;
    }
    __shared__ float sh1[8], sh2[8];
    for (int off = 16; off; off >>= 1) {
        s  += __shfl_xor_sync(0xffffffffu, s, off);
        s2 += __shfl_xor_sync(0xffffffffu, s2, off);
    }
    int w = tid >> 5, l = tid & 31;
    if (!l) { sh1[w] = s; sh2[w] = s2; }
    __syncthreads();
    if (w == 0) {
        s  = (l < 8) ? sh1[l] : 0.f;
        s2 = (l < 8) ? sh2[l] : 0.f;
        for (int off = 4; off; off >>= 1) {
            s  += __shfl_xor_sync(0xffffffffu, s, off);
            s2 += __shfl_xor_sync(0xffffffffu, s2, off);
        }
        if (!l) { sh1[0] = s; sh2[0] = s2; }
    }
    __syncthreads();
    float mu  = sh1[0] * (1.f / DIM_);
    float var = sh2[0] * (1.f / DIM_) - mu * mu;
    float inv = rsqrtf(var + 1e-5f);
#pragma unroll
    for (int i = 0; i < 4; i++) {
        int j = tid + i * 256;
        out[(size_t)t * DIM_ + j] = (v[i] - mu) * inv * g[j] + bb[j];
    }
}

// ===================== launch =====================
extern "C" void kernel_launch(void* const* d_in, const int* in_sizes, int n_in,
                              void* d_out, int out_size)
{
    const float* x        = (const float*)d_in[0];
    const float* in_proj  = (const float*)d_in[1];
    const float* conv_w   = (const float*)d_in[2];
    const float* conv_b   = (const float*)d_in[3];
    const float* xproj_w  = (const float*)d_in[4];
    const float* dtproj_w = (const float*)d_in[5];
    const float* dtproj_b = (const float*)d_in[6];
    const float* D_param  = (const float*)d_in[7];
    const float* sw       = (const float*)d_in[8];
    const float* gate_w1  = (const float*)d_in[9];
    const float* gate_w2  = (const float*)d_in[10];
    const float* out_proj = (const float*)d_in[11];
    const float* ln_g     = (const float*)d_in[12];
    const float* ln_b     = (const float*)d_in[13];
    float* out = (float*)d_out;

    float *xz, *xc, *proj, *dt, *o0, *o1, *o2, *fused, *scr;
    __nv_bfloat16 *x2, *wi2, *gw1b, *gw2b, *wob, *ctx2, *g1b, *u2;
    cudaGetSymbolAddress((void**)&xz,    g_xz);
    cudaGetSymbolAddress((void**)&xc,    g_xc);
    cudaGetSymbolAddress((void**)&proj,  g_proj);
    cudaGetSymbolAddress((void**)&dt,    g_dt);
    cudaGetSymbolAddress((void**)&o0,    g_out0);
    cudaGetSymbolAddress((void**)&o1,    g_out1);
    cudaGetSymbolAddress((void**)&o2,    g_out2);
    cudaGetSymbolAddress((void**)&fused, g_fused);
    cudaGetSymbolAddress((void**)&scr,   g_scr);
    cudaGetSymbolAddress((void**)&x2,    g_x2);
    cudaGetSymbolAddress((void**)&wi2,   g_wi2);
    cudaGetSymbolAddress((void**)&gw1b,  g_gw1b);
    cudaGetSymbolAddress((void**)&gw2b,  g_gw2b);
    cudaGetSymbolAddress((void**)&wob,   g_wob);
    cudaGetSymbolAddress((void**)&ctx2,  g_ctx2);
    cudaGetSymbolAddress((void**)&g1b,   g_g1b);
    cudaGetSymbolAddress((void**)&u2,    g_u2);

    cudaFuncSetAttribute(gemm_bf16, cudaFuncAttributeMaxDynamicSharedMemorySize, GSMEM_BYTES);

    // hi/lo conversions: x (A-mode), weights (B-mode)
    cvt_kernel<<<(1024 * 1024) / 256, 256>>>(x,        x2,   10, 1);
    cvt_kernel<<<(4096 * 1024) / 256, 256>>>(in_proj,  wi2,  10, 0);
    cvt_kernel<<<(1024 * 2048) / 256, 256>>>(gate_w1,  gw1b, 11, 0);
    cvt_kernel<<<(2048 * 1024) / 256, 256>>>(gate_w2,  gw2b, 10, 0);
    cvt_kernel<<<(1024 * 2048) / 256, 256>>>(out_proj, wob,  11, 0);

    // in_proj: xz[1024,4096] = x @ in_proj_w.T   (Ktrip=3072)
    gemm_bf16<<<dim3(32, 8, 1), 256, GSMEM_BYTES>>>(x2, wi2, 3072, 3072, xz, 4096, 0,
                                                    nullptr, 0, nullptr, nullptr, 0);

    float* outs[3] = {o0, o1, o2};
    for (int s = 0; s < 3; s++) {
        int T = T_LEN >> s;
        int stride = 1 << s;
        conv_silu_kernel<<<(T * DI) / 256, 256>>>(xz, conv_w + s * DI * 4, conv_b + s * DI, xc, T, stride);
        xproj_kernel<<<T, 256>>>(xc, xproj_w + s * 32 * DI, proj);
        dtproj_kernel<<<(T * DI) / 256, 256>>>(proj, dtproj_w + s * DI * DS, dtproj_b + s * DI, dt, T);
        scan_kernel<<<(DI * DS) / 256, 256>>>(dt, proj, xc, D_param + s * DI, outs[s], T);
    }

    fuse_kernel<<<(T_LEN * DI) / 256, 256>>>(o0, o1, o2, sw, fused, ctx2);

    // gate1: split-K x2 (3K=6144 -> 2x3072), partials to scr, combine = silu+triple
    gemm_bf16<<<dim3(8, 8, 2), 256, GSMEM_BYTES>>>(ctx2, gw1b, 3072, 6144,
                                                   scr, DIM_, (size_t)T_LEN * DIM_,
                                                   nullptr, 0, nullptr, nullptr, 0);
    comb_silu_triple<<<(T_LEN * DIM_) / 256, 256>>>(scr, scr + T_LEN * DIM_, g1b);

    // gate2: u = fused * sigmoid(g1 @ gate_w2.T) * silu(gate) -> bf16 triple (K=2048)
    gemm_bf16<<<dim3(16, 8, 1), 256, GSMEM_BYTES>>>(g1b, gw2b, 3072, 3072,
                                                    nullptr, 0, 0,
                                                    u2, 2048, fused, xz, 2);

    // out_proj: split-K x2, partials to scr; combine fused into LayerNorm
    gemm_bf16<<<dim3(8, 8, 2), 256, GSMEM_BYTES>>>(u2, wob, 3072, 6144,
                                                   scr, DIM_, (size_t)T_LEN * DIM_,
                                                   nullptr, 0, nullptr, nullptr, 0);

    ln_kernel<<<T_LEN, 256>>>(scr, scr + T_LEN * DIM_, x, ln_g, ln_b, out);
}

// round 9
// speedup vs baseline: 2.1281x; 1.1649x over previous
#include <cuda_runtime.h>
#include <cuda_bf16.h>
#include <cstdint>
#include <math.h>

#define T_LEN 1024
#define DIM_  1024
#define DI    2048
#define DS    16

// ===================== PTX helpers (family-target safe: no tcgen05) ============
__device__ __forceinline__ uint32_t smem_u32(const void* p) {
    uint32_t a;
    asm("{ .reg .u64 t; cvta.to.shared.u64 t, %1; cvt.u32.u64 %0, t; }" : "=r"(a) : "l"(p));
    return a;
}
#define CP_ASYNC16(dst, src) \
    asm volatile("cp.async.cg.shared.global [%0], [%1], 16;" :: "r"(dst), "l"(src))
#define CP_COMMIT() asm volatile("cp.async.commit_group;")
#define CP_WAIT1()  asm volatile("cp.async.wait_group 1;")
#define CP_WAIT0()  asm volatile("cp.async.wait_group 0;")

#define LDSM_X4(r0, r1, r2, r3, addr) \
    asm volatile("ldmatrix.sync.aligned.m8n8.x4.shared.b16 {%0,%1,%2,%3}, [%4];" \
                 : "=r"(r0), "=r"(r1), "=r"(r2), "=r"(r3) : "r"(addr))

#define MMA16816(c, a, b) \
    asm volatile("mma.sync.aligned.m16n8k16.row.col.f32.bf16.bf16.f32 " \
                 "{%0,%1,%2,%3},{%4,%5,%6,%7},{%8,%9},{%0,%1,%2,%3};" \
                 : "+f"((c)[0]), "+f"((c)[1]), "+f"((c)[2]), "+f"((c)[3]) \
                 : "r"((a)[0]), "r"((a)[1]), "r"((a)[2]), "r"((a)[3]), \
                   "r"((b)[0]), "r"((b)[1]))

static __device__ __forceinline__ uint32_t swz128(uint32_t off) {
    return off ^ ((off >> 3) & 0x70);
}

// ===================== scratch =====================
#define T_ALL 1792   // 1024 + 512 + 256
__device__ float g_xz[T_LEN * 4096];
__device__ float g_xcA[T_ALL * DI];
__device__ float g_projA[T_ALL * 32];
__device__ float g_dtA[T_ALL * DI];
__device__ float g_out0[T_LEN * DI];
__device__ float g_out1[(T_LEN / 2) * DI];
__device__ float g_out2[(T_LEN / 4) * DI];
__device__ float g_fused[T_LEN * DI];
__device__ float g_scr[2 * T_LEN * DIM_];   // split-K fp32 partials
// bf16 hi/lo tripled operand buffers
__device__ __nv_bfloat16 g_x2[1024 * 3072];
__device__ __nv_bfloat16 g_wi2[4096 * 3072];
__device__ __nv_bfloat16 g_gw1b[1024 * 6144];
__device__ __nv_bfloat16 g_gw2b[2048 * 3072];
__device__ __nv_bfloat16 g_wob[1024 * 6144];
__device__ __nv_bfloat16 g_ctx2[1024 * 6144];
__device__ __nv_bfloat16 g_g1b[1024 * 3072];
__device__ __nv_bfloat16 g_u2[1024 * 6144];

// ===================== math helpers =====================
__device__ __forceinline__ float sigmoidf_(float x) { return 1.f / (1.f + __expf(-x)); }
__device__ __forceinline__ float siluf_(float x)    { return x * sigmoidf_(x); }
__device__ __forceinline__ float softplusf_(float x) {
    if (x > 20.f) return x;
    return log1pf(__expf(x));
}

// per-scale row offsets into the concatenated [T_ALL, DI] buffers
__device__ __forceinline__ int scale_of_row(int tg) { return (tg < 1024) ? 0 : (tg < 1536 ? 1 : 2); }
__device__ __forceinline__ int scale_row_base(int s) { return (s == 0) ? 0 : (s == 1 ? 1024 : 1536); }

// ===================== fp32 -> bf16 hi/lo triple converters =====================
// modeA: [hi | lo | hi], modeB: [hi | hi | lo]
__global__ void cvt_kernel(const float* __restrict__ src, __nv_bfloat16* __restrict__ dst,
                           int kshift, int modeA)
{
    int i = blockIdx.x * 256 + threadIdx.x;
    int K = 1 << kshift;
    int r = i >> kshift;
    int k = i & (K - 1);
    float v = src[i];
    __nv_bfloat16 hi = __float2bfloat16(v);
    __nv_bfloat16 lo = __float2bfloat16(v - __bfloat162float(hi));
    size_t base = (size_t)r * 3 * K;
    dst[base + k] = hi;
    dst[base + K + k] = modeA ? lo : hi;
    dst[base + 2 * K + k] = modeA ? hi : lo;
}

// ===================== HMMA bf16 GEMM v2 =====================
// 128x128 CTA tile, BK=64, 4 warps (2x2), warp tile 64x64, double-buffered cp.async.
// C[m,n] = sum_k A[m,k]*B[n,k]; operands K-tripled hi/lo bf16.
// blockIdx.z slices K (A/B advance z*Kp, C advances z*czstride).
// mode 0: C = acc (fp32); mode 2: fused*sigmoid(acc)*silu(gate) -> bf16 A-triple
#define GSMEM_BYTES 66048

__device__ __forceinline__ void load_chunk(const __nv_bfloat16* gA, const __nv_bfloat16* gB,
                                           int Kstride, int c, uint32_t smA, uint32_t smB,
                                           int tid)
{
    const __nv_bfloat16* a0 = gA + c * 64;
    const __nv_bfloat16* b0 = gB + c * 64;
#pragma unroll
    for (int s = 0; s < 8; s++) {
        int e = s * 128 + tid;
        int row = e >> 3, seg = e & 7;
        CP_ASYNC16(smA + swz128(row * 128 + seg * 16), a0 + (size_t)row * Kstride + seg * 8);
    }
#pragma unroll
    for (int s = 0; s < 8; s++) {
        int e = s * 128 + tid;
        int row = e >> 3, seg = e & 7;
        CP_ASYNC16(smB + swz128(row * 128 + seg * 16), b0 + (size_t)row * Kstride + seg * 8);
    }
}

__device__ __forceinline__ void store_pair_tripleA(__nv_bfloat16* rowp, int K, int col,
                                                   float a, float b)
{
    __nv_bfloat16 ha = __float2bfloat16(a), hb = __float2bfloat16(b);
    __nv_bfloat16 la = __float2bfloat16(a - __bfloat162float(ha));
    __nv_bfloat16 lb = __float2bfloat16(b - __bfloat162float(hb));
    __nv_bfloat162 h2; h2.x = ha; h2.y = hb;
    __nv_bfloat162 l2; l2.x = la; l2.y = lb;
    *reinterpret_cast<__nv_bfloat162*>(rowp + col) = h2;
    *reinterpret_cast<__nv_bfloat162*>(rowp + K + col) = l2;
    *reinterpret_cast<__nv_bfloat162*>(rowp + 2 * K + col) = h2;
}

__global__ void __launch_bounds__(128) gemm_bf16(
    const __nv_bfloat16* __restrict__ A,
    const __nv_bfloat16* __restrict__ B,
    int Kp, int Kstride,
    float* __restrict__ C, int ldc, size_t czstride,
    __nv_bfloat16* __restrict__ Cb, int Ktrip,
    const float* __restrict__ fused, const float* __restrict__ xz,
    int mode)
{
    extern __shared__ char smem[];
    uint32_t sb = smem_u32(smem);
    const int tid = threadIdx.x, wid = tid >> 5, lane = tid & 31;
    const int wm = wid & 1, wn = wid >> 1;   // warp tile 64x64 at (wm*64, wn*64)

    const int bm = blockIdx.y << 7, bn = blockIdx.x << 7;
    const int kz = blockIdx.z;
    const __nv_bfloat16* gA = A + (size_t)bm * Kstride + (size_t)kz * Kp;
    const __nv_bfloat16* gB = B + (size_t)bn * Kstride + (size_t)kz * Kp;
    C += (size_t)kz * czstride;
    const int NC = Kp >> 6;

    const uint32_t aoff[2] = {sb, sb + 16384};
    const uint32_t boff[2] = {sb + 32768, sb + 49152};

    float acc[4][8][4];
#pragma unroll
    for (int mi = 0; mi < 4; mi++)
#pragma unroll
        for (int ni = 0; ni < 8; ni++)
#pragma unroll
            for (int q = 0; q < 4; q++) acc[mi][ni][q] = 0.f;

    const int a_row = wm * 64 + (lane & 7) + ((lane >> 3) & 1) * 8;  // + mi*16
    const int a_kh  = lane >> 4;
    const int b_row = wn * 64 + (lane & 7) + (lane >> 4) * 8;        // + nh*16
    const int b_kh  = (lane >> 3) & 1;

    load_chunk(gA, gB, Kstride, 0, aoff[0], boff[0], tid);
    CP_COMMIT();

    for (int c = 0; c < NC; c++) {
        if (c + 1 < NC) {
            load_chunk(gA, gB, Kstride, c + 1, aoff[(c + 1) & 1], boff[(c + 1) & 1], tid);
            CP_COMMIT();
            CP_WAIT1();
        } else {
            CP_WAIT0();
        }
        __syncthreads();

        const uint32_t ab = aoff[c & 1], bb = boff[c & 1];
#pragma unroll
        for (int ks = 0; ks < 4; ks++) {
            uint32_t aF[4][4];
#pragma unroll
            for (int mi = 0; mi < 4; mi++) {
                uint32_t ad = ab + swz128((uint32_t)(a_row + mi * 16) * 128 +
                                          (uint32_t)(ks * 2 + a_kh) * 16);
                LDSM_X4(aF[mi][0], aF[mi][1], aF[mi][2], aF[mi][3], ad);
            }
            uint32_t bF[8][2];
#pragma unroll
            for (int nh = 0; nh < 4; nh++) {
                uint32_t r0, r1, r2, r3;
                uint32_t bd = bb + swz128((uint32_t)(b_row + nh * 16) * 128 +
                                          (uint32_t)(ks * 2 + b_kh) * 16);
                LDSM_X4(r0, r1, r2, r3, bd);
                bF[nh * 2][0] = r0; bF[nh * 2][1] = r1;
                bF[nh * 2 + 1][0] = r2; bF[nh * 2 + 1][1] = r3;
            }
#pragma unroll
            for (int mi = 0; mi < 4; mi++)
#pragma unroll
                for (int ni = 0; ni < 8; ni++)
                    MMA16816(acc[mi][ni], aF[mi], bF[ni]);
        }
        __syncthreads();
    }

    // stage accumulators through SMEM (stride 129 -> conflict-light)
    float* cs = (float*)smem;
#pragma unroll
    for (int mi = 0; mi < 4; mi++) {
        int r0 = wm * 64 + mi * 16 + (lane >> 2);
#pragma unroll
        for (int ni = 0; ni < 8; ni++) {
            int col = wn * 64 + ni * 8 + (lane & 3) * 2;
            cs[r0 * 129 + col]           = acc[mi][ni][0];
            cs[r0 * 129 + col + 1]       = acc[mi][ni][1];
            cs[(r0 + 8) * 129 + col]     = acc[mi][ni][2];
            cs[(r0 + 8) * 129 + col + 1] = acc[mi][ni][3];
        }
    }
    __syncthreads();

    const int m = bm + tid;
    const float* crow = cs + tid * 129;
    if (mode == 0) {
        float* orow = C + (size_t)m * ldc + bn;
#pragma unroll 8
        for (int kk = 0; kk < 32; kk++) {
            float4 v = make_float4(crow[kk * 4], crow[kk * 4 + 1],
                                   crow[kk * 4 + 2], crow[kk * 4 + 3]);
            *reinterpret_cast<float4*>(orow + kk * 4) = v;
        }
    } else {
        __nv_bfloat16* orow = Cb + (size_t)m * 3 * Ktrip + bn;
        const float* frow = fused + (size_t)m * 2048 + bn;
        const float* grow = xz + (size_t)m * 4096 + 2048 + bn;
#pragma unroll 8
        for (int kk = 0; kk < 64; kk++) {
            float a = frow[kk * 2]     * sigmoidf_(crow[kk * 2])     * siluf_(grow[kk * 2]);
            float b = frow[kk * 2 + 1] * sigmoidf_(crow[kk * 2 + 1]) * siluf_(grow[kk * 2 + 1]);
            store_pair_tripleA(orow, Ktrip, kk * 2, a, b);
        }
    }
}

// ===================== split-K combiner (gate1) =====================
__global__ void comb_silu_triple(const float* __restrict__ p0,
                                 const float* __restrict__ p1,
                                 __nv_bfloat16* __restrict__ g1b)
{
    int i = blockIdx.x * 256 + threadIdx.x;
    if (i >= T_LEN * DIM_) return;
    int m = i >> 10, k = i & 1023;
    float v = siluf_(p0[i] + p1[i]);
    __nv_bfloat16 hi = __float2bfloat16(v);
    __nv_bfloat16 lo = __float2bfloat16(v - __bfloat162float(hi));
    __nv_bfloat16* rowp = g1b + (size_t)m * 3072;
    rowp[k] = hi;
    rowp[1024 + k] = lo;
    rowp[2048 + k] = hi;
}

// ===================== merged per-scale kernels =====================
// conv+silu for ALL scales in one launch; rows [0,1024)=s0, [1024,1536)=s1, [1536,1792)=s2
__global__ void conv_silu_all(const float* __restrict__ xz,
                              const float* __restrict__ conv_w,
                              const float* __restrict__ conv_b,
                              float* __restrict__ xcA)
{
    int idx = blockIdx.x * blockDim.x + threadIdx.x;
    if (idx >= T_ALL * DI) return;
    int tg = idx >> 11;
    int d = idx & (DI - 1);
    int s = scale_of_row(tg);
    int t = tg - scale_row_base(s);
    int stride = 1 << s;
    const float* cw = conv_w + s * DI * 4;
    float4 w4 = *reinterpret_cast<const float4*>(cw + d * 4);
    float wk[4] = {w4.x, w4.y, w4.z, w4.w};
    float acc = conv_b[s * DI + d];
    float inv = 1.f / (float)stride;
#pragma unroll
    for (int k = 0; k < 4; k++) {
        int tt = t - 3 + k;
        if (tt >= 0) {
            float v = 0.f;
            int base = tt * stride;
            for (int r = 0; r < stride; r++) v += xz[(size_t)(base + r) * 4096 + d];
            acc += wk[k] * (v * inv);
        }
    }
    xcA[idx] = siluf_(acc);
}

// xc @ xproj_w.T for all scales: one block per global row
__global__ void xproj_all(const float* __restrict__ xcA,
                          const float* __restrict__ xproj_w,
                          float* __restrict__ projA)
{
    int tg = blockIdx.x;
    int s = scale_of_row(tg);
    const float* W = xproj_w + s * 32 * DI;
    __shared__ float sx[DI];
    for (int i = threadIdx.x; i < DI; i += 256) sx[i] = xcA[(size_t)tg * DI + i];
    __syncthreads();
    int warp = threadIdx.x >> 5, lane = threadIdx.x & 31;
    for (int j = warp; j < 32; j += 8) {
        const float* w = W + (size_t)j * DI;
        float acc = 0.f;
        for (int i = lane * 4; i < DI; i += 128) {
            float4 a = *reinterpret_cast<const float4*>(&sx[i]);
            float4 b = *reinterpret_cast<const float4*>(&w[i]);
            acc += a.x * b.x + a.y * b.y + a.z * b.z + a.w * b.w;
        }
        for (int off = 16; off; off >>= 1) acc += __shfl_xor_sync(0xffffffffu, acc, off);
        if (!lane) projA[tg * 32 + j] = acc;
    }
}

__global__ void dtproj_all(const float* __restrict__ projA,
                           const float* __restrict__ dtproj_w,
                           const float* __restrict__ dtproj_b,
                           float* __restrict__ dtA)
{
    int idx = blockIdx.x * blockDim.x + threadIdx.x;
    if (idx >= T_ALL * DI) return;
    int tg = idx >> 11;
    int d = idx & (DI - 1);
    int s = scale_of_row(tg);
    const float* bp = projA + tg * 32;
    const float4* w4 = reinterpret_cast<const float4*>(dtproj_w + (size_t)(s * DI + d) * 16);
    float acc = dtproj_b[s * DI + d];
#pragma unroll
    for (int q = 0; q < 4; q++) {
        float4 w = w4[q];
        acc += bp[q * 4 + 0] * w.x + bp[q * 4 + 1] * w.y +
               bp[q * 4 + 2] * w.z + bp[q * 4 + 3] * w.w;
    }
    dtA[idx] = softplusf_(softplusf_(acc));
}

// selective scan, all scales in one launch (384 blocks: 128 per scale)
__global__ void scan_all(const float* __restrict__ dtA,
                         const float* __restrict__ projA,
                         const float* __restrict__ xcA,
                         const float* __restrict__ D_param,
                         float* __restrict__ y0,
                         float* __restrict__ y1,
                         float* __restrict__ y2)
{
    int s = blockIdx.x >> 7;
    int gid = (blockIdx.x & 127) * 256 + threadIdx.x;
    int n = gid & 15;
    int d = gid >> 4;
    int T = T_LEN >> s;
    int rb = scale_row_base(s);
    const float* dt   = dtA   + (size_t)rb * DI;
    const float* xc   = xcA   + (size_t)rb * DI;
    const float* proj = projA + rb * 32;
    float* y = (s == 0) ? y0 : (s == 1 ? y1 : y2);
    float An = -(float)(n + 1);
    float Dpd = D_param[s * DI + d];
    float h = 0.f;
    for (int t = 0; t < T; t += 4) {
        float v[4], xcs[4];
#pragma unroll
        for (int q = 0; q < 4; q++) {
            int tt = t + q;
            float dtv = dt[(size_t)tt * DI + d];
            float xcv = xc[(size_t)tt * DI + d];
            float Bv  = proj[tt * 32 + n];
            float Cv  = proj[tt * 32 + 16 + n];
            float dA  = fmaxf(__expf(dtv * An), 1e-38f);
            float dBx = fmaxf(dtv * Bv * xcv, 1e-38f);
            h = dA * h + dBx;
            v[q] = Cv * h;
            xcs[q] = xcv;
        }
#pragma unroll
        for (int off = 8; off; off >>= 1) {
#pragma unroll
            for (int q = 0; q < 4; q++)
                v[q] += __shfl_xor_sync(0xffffffffu, v[q], off);
        }
        if (n == 0) {
#pragma unroll
            for (int q = 0; q < 4; q++)
                y[(size_t)(t + q) * DI + d] = v[q] + Dpd * xcs[q];
        }
    }
}

__device__ __forceinline__ float upsample_read(const float* __restrict__ y,
                                               int Tin, int t, int d)
{
    if (Tin == T_LEN) return y[(size_t)t * DI + d];
    float scale = (float)Tin / (float)T_LEN;
    float pos = ((float)t + 0.5f) * scale - 0.5f;
    pos = fminf(fmaxf(pos, 0.f), (float)(Tin - 1));
    int lo = (int)floorf(pos);
    int hi = min(lo + 1, Tin - 1);
    float w = pos - (float)lo;
    return y[(size_t)lo * DI + d] * (1.f - w) + y[(size_t)hi * DI + d] * w;
}

__global__ void fuse_kernel(const float* __restrict__ y0,
                            const float* __restrict__ y1,
                            const float* __restrict__ y2,
                            const float* __restrict__ sw,
                            float* __restrict__ fused,
                            __nv_bfloat16* __restrict__ ctx2)
{
    int idx = blockIdx.x * blockDim.x + threadIdx.x;
    if (idx >= T_LEN * DI) return;
    int t = idx >> 11, d = idx & (DI - 1);
    float w0 = sw[0], w1 = sw[1], w2 = sw[2];
    float m = fmaxf(w0, fmaxf(w1, w2));
    float e0 = __expf(w0 - m), e1 = __expf(w1 - m), e2 = __expf(w2 - m);
    float inv = 1.f / (e0 + e1 + e2);
    float u0 = y0[idx];
    float u1 = upsample_read(y1, T_LEN / 2, t, d);
    float u2 = upsample_read(y2, T_LEN / 4, t, d);
    fused[idx] = (e0 * u0 + e1 * u1 + e2 * u2) * inv;
    float v = (u0 + u1 + u2) * (1.f / 3.f);
    __nv_bfloat16 hi = __float2bfloat16(v);
    __nv_bfloat16 lo = __float2bfloat16(v - __bfloat162float(hi));
    size_t base = (size_t)t * 6144;
    ctx2[base + d] = hi;
    ctx2[base + 2048 + d] = lo;
    ctx2[base + 4096 + d] = hi;
}

// residual + LayerNorm, fused with out_proj split-K combine: y = p0 + p1 + x
__global__ void ln_kernel(const float* __restrict__ p0,
                          const float* __restrict__ p1,
                          const float* __restrict__ x,
                          const float* __restrict__ g,
                          const float* __restrict__ bb,
                          float* __restrict__ out)
{
    int t = blockIdx.x;
    int tid = threadIdx.x;
    float v[4];
    float s = 0.f, s2 = 0.f;
#pragma unroll
    for (int i = 0; i < 4; i++) {
        int j = tid + i * 256;
        size_t off = (size_t)t * DIM_ + j;
        float y = p0[off] + p1[off] + x[off];
        v[i] = y; s += y; s2 += y * y;
    }
    __shared__ float sh1[8], sh2[8];
    for (int off = 16; off; off >>= 1) {
        s  += __shfl_xor_sync(0xffffffffu, s, off);
        s2 += __shfl_xor_sync(0xffffffffu, s2, off);
    }
    int w = tid >> 5, l = tid & 31;
    if (!l) { sh1[w] = s; sh2[w] = s2; }
    __syncthreads();
    if (w == 0) {
        s  = (l < 8) ? sh1[l] : 0.f;
        s2 = (l < 8) ? sh2[l] : 0.f;
        for (int off = 4; off; off >>= 1) {
            s  += __shfl_xor_sync(0xffffffffu, s, off);
            s2 += __shfl_xor_sync(0xffffffffu, s2, off);
        }
        if (!l) { sh1[0] = s; sh2[0] = s2; }
    }
    __syncthreads();
    float mu  = sh1[0] * (1.f / DIM_);
    float var = sh2[0] * (1.f / DIM_) - mu * mu;
    float inv = rsqrtf(var + 1e-5f);
#pragma unroll
    for (int i = 0; i < 4; i++) {
        int j = tid + i * 256;
        out[(size_t)t * DIM_ + j] = (v[i] - mu) * inv * g[j] + bb[j];
    }
}

// ===================== launch =====================
extern "C" void kernel_launch(void* const* d_in, const int* in_sizes, int n_in,
                              void* d_out, int out_size)
{
    const float* x        = (const float*)d_in[0];
    const float* in_proj  = (const float*)d_in[1];
    const float* conv_w   = (const float*)d_in[2];
    const float* conv_b   = (const float*)d_in[3];
    const float* xproj_w  = (const float*)d_in[4];
    const float* dtproj_w = (const float*)d_in[5];
    const float* dtproj_b = (const float*)d_in[6];
    const float* D_param  = (const float*)d_in[7];
    const float* sw       = (const float*)d_in[8];
    const float* gate_w1  = (const float*)d_in[9];
    const float* gate_w2  = (const float*)d_in[10];
    const float* out_proj = (const float*)d_in[11];
    const float* ln_g     = (const float*)d_in[12];
    const float* ln_b     = (const float*)d_in[13];
    float* out = (float*)d_out;

    float *xz, *xcA, *projA, *dtA, *o0, *o1, *o2, *fused, *scr;
    __nv_bfloat16 *x2, *wi2, *gw1b, *gw2b, *wob, *ctx2, *g1b, *u2;
    cudaGetSymbolAddress((void**)&xz,    g_xz);
    cudaGetSymbolAddress((void**)&xcA,   g_xcA);
    cudaGetSymbolAddress((void**)&projA, g_projA);
    cudaGetSymbolAddress((void**)&dtA,   g_dtA);
    cudaGetSymbolAddress((void**)&o0,    g_out0);
    cudaGetSymbolAddress((void**)&o1,    g_out1);
    cudaGetSymbolAddress((void**)&o2,    g_out2);
    cudaGetSymbolAddress((void**)&fused, g_fused);
    cudaGetSymbolAddress((void**)&scr,   g_scr);
    cudaGetSymbolAddress((void**)&x2,    g_x2);
    cudaGetSymbolAddress((void**)&wi2,   g_wi2);
    cudaGetSymbolAddress((void**)&gw1b,  g_gw1b);
    cudaGetSymbolAddress((void**)&gw2b,  g_gw2b);
    cudaGetSymbolAddress((void**)&wob,   g_wob);
    cudaGetSymbolAddress((void**)&ctx2,  g_ctx2);
    cudaGetSymbolAddress((void**)&g1b,   g_g1b);
    cudaGetSymbolAddress((void**)&u2,    g_u2);

    cudaFuncSetAttribute(gemm_bf16, cudaFuncAttributeMaxDynamicSharedMemorySize, GSMEM_BYTES);

    // hi/lo conversions: x (A-mode), weights (B-mode)
    cvt_kernel<<<(1024 * 1024) / 256, 256>>>(x,        x2,   10, 1);
    cvt_kernel<<<(4096 * 1024) / 256, 256>>>(in_proj,  wi2,  10, 0);
    cvt_kernel<<<(1024 * 2048) / 256, 256>>>(gate_w1,  gw1b, 11, 0);
    cvt_kernel<<<(2048 * 1024) / 256, 256>>>(gate_w2,  gw2b, 10, 0);
    cvt_kernel<<<(1024 * 2048) / 256, 256>>>(out_proj, wob,  11, 0);

    // in_proj: xz[1024,4096] = x @ in_proj_w.T   (Ktrip=3072)
    gemm_bf16<<<dim3(32, 8, 1), 128, GSMEM_BYTES>>>(x2, wi2, 3072, 3072, xz, 4096, 0,
                                                    nullptr, 0, nullptr, nullptr, 0);

    // merged per-scale pipeline (all 3 scales per launch)
    conv_silu_all<<<(T_ALL * DI) / 256, 256>>>(xz, conv_w, conv_b, xcA);
    xproj_all<<<T_ALL, 256>>>(xcA, xproj_w, projA);
    dtproj_all<<<(T_ALL * DI) / 256, 256>>>(projA, dtproj_w, dtproj_b, dtA);
    scan_all<<<384, 256>>>(dtA, projA, xcA, D_param, o0, o1, o2);

    fuse_kernel<<<(T_LEN * DI) / 256, 256>>>(o0, o1, o2, sw, fused, ctx2);

    // gate1: split-K x2 (3K=6144 -> 2x3072), partials to scr, combine = silu+triple
    gemm_bf16<<<dim3(8, 8, 2), 128, GSMEM_BYTES>>>(ctx2, gw1b, 3072, 6144,
                                                   scr, DIM_, (size_t)T_LEN * DIM_,
                                                   nullptr, 0, nullptr, nullptr, 0);
    comb_silu_triple<<<(T_LEN * DIM_) / 256, 256>>>(scr, scr + T_LEN * DIM_, g1b);

    // gate2: u = fused * sigmoid(g1 @ gate_w2.T) * silu(gate) -> bf16 triple (K=2048)
    gemm_bf16<<<dim3(16, 8, 1), 128, GSMEM_BYTES>>>(g1b, gw2b, 3072, 3072,
                                                    nullptr, 0, 0,
                                                    u2, 2048, fused, xz, 2);

    // out_proj: split-K x2, partials to scr; combine fused into LayerNorm
    gemm_bf16<<<dim3(8, 8, 2), 128, GSMEM_BYTES>>>(u2, wob, 3072, 6144,
                                                   scr, DIM_, (size_t)T_LEN * DIM_,
                                                   nullptr, 0, nullptr, nullptr, 0);

    ln_kernel<<<T_LEN, 256>>>(scr, scr + T_LEN * DIM_, x, ln_g, ln_b, out);
}

// round 10
// speedup vs baseline: 2.4243x; 1.1392x over previous
#include <cuda_runtime.h>
#include <cuda_fp16.h>
#include <cstdint>
#include <math.h>

#define T_LEN 1024
#define DIM_  1024
#define DI    2048
#define DS    16

// ===================== PTX helpers (family-target safe: no tcgen05) ============
__device__ __forceinline__ uint32_t smem_u32(const void* p) {
    uint32_t a;
    asm("{ .reg .u64 t; cvta.to.shared.u64 t, %1; cvt.u32.u64 %0, t; }" : "=r"(a) : "l"(p));
    return a;
}
#define CP_ASYNC16(dst, src) \
    asm volatile("cp.async.cg.shared.global [%0], [%1], 16;" :: "r"(dst), "l"(src))
#define CP_COMMIT() asm volatile("cp.async.commit_group;")
#define CP_WAIT1()  asm volatile("cp.async.wait_group 1;")
#define CP_WAIT0()  asm volatile("cp.async.wait_group 0;")

#define LDSM_X4(r0, r1, r2, r3, addr) \
    asm volatile("ldmatrix.sync.aligned.m8n8.x4.shared.b16 {%0,%1,%2,%3}, [%4];" \
                 : "=r"(r0), "=r"(r1), "=r"(r2), "=r"(r3) : "r"(addr))

#define MMA16816(c, a, b) \
    asm volatile("mma.sync.aligned.m16n8k16.row.col.f32.f16.f16.f32 " \
                 "{%0,%1,%2,%3},{%4,%5,%6,%7},{%8,%9},{%0,%1,%2,%3};" \
                 : "+f"((c)[0]), "+f"((c)[1]), "+f"((c)[2]), "+f"((c)[3]) \
                 : "r"((a)[0]), "r"((a)[1]), "r"((a)[2]), "r"((a)[3]), \
                   "r"((b)[0]), "r"((b)[1]))

static __device__ __forceinline__ uint32_t swz128(uint32_t off) {
    return off ^ ((off >> 3) & 0x70);
}

// ===================== scratch =====================
#define T_ALL 1792   // 1024 + 512 + 256
__device__ float g_xz[T_LEN * 4096];
__device__ float g_xcA[T_ALL * DI];
__device__ float g_projA[T_ALL * 32];
__device__ float g_dtA[T_ALL * DI];
__device__ float g_out0[T_LEN * DI];
__device__ float g_out1[(T_LEN / 2) * DI];
__device__ float g_out2[(T_LEN / 4) * DI];
__device__ float g_fused[T_LEN * DI];
__device__ float g_scr[2 * T_LEN * DIM_];   // split-K fp32 partials
// fp16 hi/lo paired operand buffers (A: [hi|lo], B: [hi|hi])
__device__ __half g_x2[1024 * 2048];
__device__ __half g_wi2[4096 * 2048];
__device__ __half g_gw1b[1024 * 4096];
__device__ __half g_gw2b[2048 * 2048];
__device__ __half g_wob[1024 * 4096];
__device__ __half g_ctx2[1024 * 4096];
__device__ __half g_g1b[1024 * 2048];
__device__ __half g_u2[1024 * 4096];

// ===================== math helpers =====================
__device__ __forceinline__ float sigmoidf_(float x) { return 1.f / (1.f + __expf(-x)); }
__device__ __forceinline__ float siluf_(float x)    { return x * sigmoidf_(x); }
__device__ __forceinline__ float softplusf_(float x) {
    if (x > 20.f) return x;
    return log1pf(__expf(x));
}

// per-scale row offsets into the concatenated [T_ALL, DI] buffers
__device__ __forceinline__ int scale_of_row(int tg) { return (tg < 1024) ? 0 : (tg < 1536 ? 1 : 2); }
__device__ __forceinline__ int scale_row_base(int s) { return (s == 0) ? 0 : (s == 1 ? 1024 : 1536); }

// ===================== fp32 -> fp16 hi/lo pair converters =====================
// modeA: [hi | lo], modeB: [hi | hi]
__global__ void cvt_kernel(const float* __restrict__ src, __half* __restrict__ dst,
                           int kshift, int modeA)
{
    int i = blockIdx.x * 256 + threadIdx.x;
    int K = 1 << kshift;
    int r = i >> kshift;
    int k = i & (K - 1);
    float v = src[i];
    __half hi = __float2half(v);
    __half lo = __float2half(v - __half2float(hi));
    size_t base = (size_t)r * 2 * K;
    dst[base + k] = hi;
    dst[base + K + k] = modeA ? lo : hi;
}

// ===================== HMMA fp16 GEMM =====================
// 128x128 CTA tile, BK=64, 4 warps (2x2), warp tile 64x64, double-buffered cp.async.
// C[m,n] = sum_k A[m,k]*B[n,k]; operands K-paired hi/lo fp16 (A=[hi|lo], B=[hi|hi]).
// blockIdx.z slices K (A/B advance z*Kp, C advances z*czstride).
// mode 0: C = acc (fp32); mode 2: fused*sigmoid(acc)*silu(gate) -> fp16 A-pair
#define GSMEM_BYTES 66048

__device__ __forceinline__ void load_chunk(const __half* gA, const __half* gB,
                                           int Kstride, int c, uint32_t smA, uint32_t smB,
                                           int tid)
{
    const __half* a0 = gA + c * 64;
    const __half* b0 = gB + c * 64;
#pragma unroll
    for (int s = 0; s < 8; s++) {
        int e = s * 128 + tid;
        int row = e >> 3, seg = e & 7;
        CP_ASYNC16(smA + swz128(row * 128 + seg * 16), a0 + (size_t)row * Kstride + seg * 8);
    }
#pragma unroll
    for (int s = 0; s < 8; s++) {
        int e = s * 128 + tid;
        int row = e >> 3, seg = e & 7;
        CP_ASYNC16(smB + swz128(row * 128 + seg * 16), b0 + (size_t)row * Kstride + seg * 8);
    }
}

__device__ __forceinline__ void store_pair2(__half* rowp, int K, int col, float a, float b)
{
    __half ha = __float2half(a), hb = __float2half(b);
    __half la = __float2half(a - __half2float(ha));
    __half lb = __float2half(b - __half2float(hb));
    __half2 h2; h2.x = ha; h2.y = hb;
    __half2 l2; l2.x = la; l2.y = lb;
    *reinterpret_cast<__half2*>(rowp + col) = h2;
    *reinterpret_cast<__half2*>(rowp + K + col) = l2;
}

__global__ void __launch_bounds__(128) gemm_fp16(
    const __half* __restrict__ A,
    const __half* __restrict__ B,
    int Kp, int Kstride,
    float* __restrict__ C, int ldc, size_t czstride,
    __half* __restrict__ Cb, int Kpair,
    const float* __restrict__ fused, const float* __restrict__ xz,
    int mode)
{
    extern __shared__ char smem[];
    uint32_t sb = smem_u32(smem);
    const int tid = threadIdx.x, wid = tid >> 5, lane = tid & 31;
    const int wm = wid & 1, wn = wid >> 1;   // warp tile 64x64 at (wm*64, wn*64)

    const int bm = blockIdx.y << 7, bn = blockIdx.x << 7;
    const int kz = blockIdx.z;
    const __half* gA = A + (size_t)bm * Kstride + (size_t)kz * Kp;
    const __half* gB = B + (size_t)bn * Kstride + (size_t)kz * Kp;
    C += (size_t)kz * czstride;
    const int NC = Kp >> 6;

    const uint32_t aoff[2] = {sb, sb + 16384};
    const uint32_t boff[2] = {sb + 32768, sb + 49152};

    float acc[4][8][4];
#pragma unroll
    for (int mi = 0; mi < 4; mi++)
#pragma unroll
        for (int ni = 0; ni < 8; ni++)
#pragma unroll
            for (int q = 0; q < 4; q++) acc[mi][ni][q] = 0.f;

    const int a_row = wm * 64 + (lane & 7) + ((lane >> 3) & 1) * 8;  // + mi*16
    const int a_kh  = lane >> 4;
    const int b_row = wn * 64 + (lane & 7) + (lane >> 4) * 8;        // + nh*16
    const int b_kh  = (lane >> 3) & 1;

    load_chunk(gA, gB, Kstride, 0, aoff[0], boff[0], tid);
    CP_COMMIT();

    for (int c = 0; c < NC; c++) {
        if (c + 1 < NC) {
            load_chunk(gA, gB, Kstride, c + 1, aoff[(c + 1) & 1], boff[(c + 1) & 1], tid);
            CP_COMMIT();
            CP_WAIT1();
        } else {
            CP_WAIT0();
        }
        __syncthreads();

        const uint32_t ab = aoff[c & 1], bb = boff[c & 1];
#pragma unroll
        for (int ks = 0; ks < 4; ks++) {
            uint32_t aF[4][4];
#pragma unroll
            for (int mi = 0; mi < 4; mi++) {
                uint32_t ad = ab + swz128((uint32_t)(a_row + mi * 16) * 128 +
                                          (uint32_t)(ks * 2 + a_kh) * 16);
                LDSM_X4(aF[mi][0], aF[mi][1], aF[mi][2], aF[mi][3], ad);
            }
            uint32_t bF[8][2];
#pragma unroll
            for (int nh = 0; nh < 4; nh++) {
                uint32_t r0, r1, r2, r3;
                uint32_t bd = bb + swz128((uint32_t)(b_row + nh * 16) * 128 +
                                          (uint32_t)(ks * 2 + b_kh) * 16);
                LDSM_X4(r0, r1, r2, r3, bd);
                bF[nh * 2][0] = r0; bF[nh * 2][1] = r1;
                bF[nh * 2 + 1][0] = r2; bF[nh * 2 + 1][1] = r3;
            }
#pragma unroll
            for (int mi = 0; mi < 4; mi++)
#pragma unroll
                for (int ni = 0; ni < 8; ni++)
                    MMA16816(acc[mi][ni], aF[mi], bF[ni]);
        }
        __syncthreads();
    }

    // stage accumulators through SMEM (stride 129 -> conflict-light)
    float* cs = (float*)smem;
#pragma unroll
    for (int mi = 0; mi < 4; mi++) {
        int r0 = wm * 64 + mi * 16 + (lane >> 2);
#pragma unroll
        for (int ni = 0; ni < 8; ni++) {
            int col = wn * 64 + ni * 8 + (lane & 3) * 2;
            cs[r0 * 129 + col]           = acc[mi][ni][0];
            cs[r0 * 129 + col + 1]       = acc[mi][ni][1];
            cs[(r0 + 8) * 129 + col]     = acc[mi][ni][2];
            cs[(r0 + 8) * 129 + col + 1] = acc[mi][ni][3];
        }
    }
    __syncthreads();

    const int m = bm + tid;
    const float* crow = cs + tid * 129;
    if (mode == 0) {
        float* orow = C + (size_t)m * ldc + bn;
#pragma unroll 8
        for (int kk = 0; kk < 32; kk++) {
            float4 v = make_float4(crow[kk * 4], crow[kk * 4 + 1],
                                   crow[kk * 4 + 2], crow[kk * 4 + 3]);
            *reinterpret_cast<float4*>(orow + kk * 4) = v;
        }
    } else {
        __half* orow = Cb + (size_t)m * 2 * Kpair + bn;
        const float* frow = fused + (size_t)m * 2048 + bn;
        const float* grow = xz + (size_t)m * 4096 + 2048 + bn;
#pragma unroll 8
        for (int kk = 0; kk < 64; kk++) {
            float a = frow[kk * 2]     * sigmoidf_(crow[kk * 2])     * siluf_(grow[kk * 2]);
            float b = frow[kk * 2 + 1] * sigmoidf_(crow[kk * 2 + 1]) * siluf_(grow[kk * 2 + 1]);
            store_pair2(orow, Kpair, kk * 2, a, b);
        }
    }
}

// ===================== split-K combiner (gate1) =====================
// g1 = silu(p0 + p1) -> fp16 A-pair rows of length 2*1024 into g1b
__global__ void comb_silu_pair(const float* __restrict__ p0,
                               const float* __restrict__ p1,
                               __half* __restrict__ g1b)
{
    int i = blockIdx.x * 256 + threadIdx.x;
    if (i >= T_LEN * DIM_) return;
    int m = i >> 10, k = i & 1023;
    float v = siluf_(p0[i] + p1[i]);
    __half hi = __float2half(v);
    __half lo = __float2half(v - __half2float(hi));
    __half* rowp = g1b + (size_t)m * 2048;
    rowp[k] = hi;
    rowp[1024 + k] = lo;
}

// ===================== merged per-scale kernels =====================
__global__ void conv_silu_all(const float* __restrict__ xz,
                              const float* __restrict__ conv_w,
                              const float* __restrict__ conv_b,
                              float* __restrict__ xcA)
{
    int idx = blockIdx.x * blockDim.x + threadIdx.x;
    if (idx >= T_ALL * DI) return;
    int tg = idx >> 11;
    int d = idx & (DI - 1);
    int s = scale_of_row(tg);
    int t = tg - scale_row_base(s);
    int stride = 1 << s;
    const float* cw = conv_w + s * DI * 4;
    float4 w4 = *reinterpret_cast<const float4*>(cw + d * 4);
    float wk[4] = {w4.x, w4.y, w4.z, w4.w};
    float acc = conv_b[s * DI + d];
    float inv = 1.f / (float)stride;
#pragma unroll
    for (int k = 0; k < 4; k++) {
        int tt = t - 3 + k;
        if (tt >= 0) {
            float v = 0.f;
            int base = tt * stride;
            for (int r = 0; r < stride; r++) v += xz[(size_t)(base + r) * 4096 + d];
            acc += wk[k] * (v * inv);
        }
    }
    xcA[idx] = siluf_(acc);
}

__global__ void xproj_all(const float* __restrict__ xcA,
                          const float* __restrict__ xproj_w,
                          float* __restrict__ projA)
{
    int tg = blockIdx.x;
    int s = scale_of_row(tg);
    const float* W = xproj_w + s * 32 * DI;
    __shared__ float sx[DI];
    for (int i = threadIdx.x; i < DI; i += 256) sx[i] = xcA[(size_t)tg * DI + i];
    __syncthreads();
    int warp = threadIdx.x >> 5, lane = threadIdx.x & 31;
    for (int j = warp; j < 32; j += 8) {
        const float* w = W + (size_t)j * DI;
        float acc = 0.f;
        for (int i = lane * 4; i < DI; i += 128) {
            float4 a = *reinterpret_cast<const float4*>(&sx[i]);
            float4 b = *reinterpret_cast<const float4*>(&w[i]);
            acc += a.x * b.x + a.y * b.y + a.z * b.z + a.w * b.w;
        }
        for (int off = 16; off; off >>= 1) acc += __shfl_xor_sync(0xffffffffu, acc, off);
        if (!lane) projA[tg * 32 + j] = acc;
    }
}

__global__ void dtproj_all(const float* __restrict__ projA,
                           const float* __restrict__ dtproj_w,
                           const float* __restrict__ dtproj_b,
                           float* __restrict__ dtA)
{
    int idx = blockIdx.x * blockDim.x + threadIdx.x;
    if (idx >= T_ALL * DI) return;
    int tg = idx >> 11;
    int d = idx & (DI - 1);
    int s = scale_of_row(tg);
    const float* bp = projA + tg * 32;
    const float4* w4 = reinterpret_cast<const float4*>(dtproj_w + (size_t)(s * DI + d) * 16);
    float acc = dtproj_b[s * DI + d];
#pragma unroll
    for (int q = 0; q < 4; q++) {
        float4 w = w4[q];
        acc += bp[q * 4 + 0] * w.x + bp[q * 4 + 1] * w.y +
               bp[q * 4 + 2] * w.z + bp[q * 4 + 3] * w.w;
    }
    dtA[idx] = softplusf_(softplusf_(acc));
}

// selective scan, all scales in one launch (384 blocks: 128 per scale)
__global__ void scan_all(const float* __restrict__ dtA,
                         const float* __restrict__ projA,
                         const float* __restrict__ xcA,
                         const float* __restrict__ D_param,
                         float* __restrict__ y0,
                         float* __restrict__ y1,
                         float* __restrict__ y2)
{
    int s = blockIdx.x >> 7;
    int gid = (blockIdx.x & 127) * 256 + threadIdx.x;
    int n = gid & 15;
    int d = gid >> 4;
    int T = T_LEN >> s;
    int rb = scale_row_base(s);
    const float* dt   = dtA   + (size_t)rb * DI;
    const float* xc   = xcA   + (size_t)rb * DI;
    const float* proj = projA + rb * 32;
    float* y = (s == 0) ? y0 : (s == 1 ? y1 : y2);
    float An = -(float)(n + 1);
    float Dpd = D_param[s * DI + d];
    float h = 0.f;
    for (int t = 0; t < T; t += 4) {
        float v[4], xcs[4];
#pragma unroll
        for (int q = 0; q < 4; q++) {
            int tt = t + q;
            float dtv = dt[(size_t)tt * DI + d];
            float xcv = xc[(size_t)tt * DI + d];
            float Bv  = proj[tt * 32 + n];
            float Cv  = proj[tt * 32 + 16 + n];
            float dA  = fmaxf(__expf(dtv * An), 1e-38f);
            float dBx = fmaxf(dtv * Bv * xcv, 1e-38f);
            h = dA * h + dBx;
            v[q] = Cv * h;
            xcs[q] = xcv;
        }
#pragma unroll
        for (int off = 8; off; off >>= 1) {
#pragma unroll
            for (int q = 0; q < 4; q++)
                v[q] += __shfl_xor_sync(0xffffffffu, v[q], off);
        }
        if (n == 0) {
#pragma unroll
            for (int q = 0; q < 4; q++)
                y[(size_t)(t + q) * DI + d] = v[q] + Dpd * xcs[q];
        }
    }
}

__device__ __forceinline__ float upsample_read(const float* __restrict__ y,
                                               int Tin, int t, int d)
{
    if (Tin == T_LEN) return y[(size_t)t * DI + d];
    float scale = (float)Tin / (float)T_LEN;
    float pos = ((float)t + 0.5f) * scale - 0.5f;
    pos = fminf(fmaxf(pos, 0.f), (float)(Tin - 1));
    int lo = (int)floorf(pos);
    int hi = min(lo + 1, Tin - 1);
    float w = pos - (float)lo;
    return y[(size_t)lo * DI + d] * (1.f - w) + y[(size_t)hi * DI + d] * w;
}

// fused (fp32) + ctx as fp16 A-pair (K=2048) for the gate1 GEMM
__global__ void fuse_kernel(const float* __restrict__ y0,
                            const float* __restrict__ y1,
                            const float* __restrict__ y2,
                            const float* __restrict__ sw,
                            float* __restrict__ fused,
                            __half* __restrict__ ctx2)
{
    int idx = blockIdx.x * blockDim.x + threadIdx.x;
    if (idx >= T_LEN * DI) return;
    int t = idx >> 11, d = idx & (DI - 1);
    float w0 = sw[0], w1 = sw[1], w2 = sw[2];
    float m = fmaxf(w0, fmaxf(w1, w2));
    float e0 = __expf(w0 - m), e1 = __expf(w1 - m), e2 = __expf(w2 - m);
    float inv = 1.f / (e0 + e1 + e2);
    float u0 = y0[idx];
    float u1 = upsample_read(y1, T_LEN / 2, t, d);
    float u2 = upsample_read(y2, T_LEN / 4, t, d);
    fused[idx] = (e0 * u0 + e1 * u1 + e2 * u2) * inv;
    float v = (u0 + u1 + u2) * (1.f / 3.f);
    __half hi = __float2half(v);
    __half lo = __float2half(v - __half2float(hi));
    size_t base = (size_t)t * 4096;
    ctx2[base + d] = hi;
    ctx2[base + 2048 + d] = lo;
}

// residual + LayerNorm, fused with out_proj split-K combine: y = p0 + p1 + x
__global__ void ln_kernel(const float* __restrict__ p0,
                          const float* __restrict__ p1,
                          const float* __restrict__ x,
                          const float* __restrict__ g,
                          const float* __restrict__ bb,
                          float* __restrict__ out)
{
    int t = blockIdx.x;
    int tid = threadIdx.x;
    float v[4];
    float s = 0.f, s2 = 0.f;
#pragma unroll
    for (int i = 0; i < 4; i++) {
        int j = tid + i * 256;
        size_t off = (size_t)t * DIM_ + j;
        float y = p0[off] + p1[off] + x[off];
        v[i] = y; s += y; s2 += y * y;
    }
    __shared__ float sh1[8], sh2[8];
    for (int off = 16; off; off >>= 1) {
        s  += __shfl_xor_sync(0xffffffffu, s, off);
        s2 += __shfl_xor_sync(0xffffffffu, s2, off);
    }
    int w = tid >> 5, l = tid & 31;
    if (!l) { sh1[w] = s; sh2[w] = s2; }
    __syncthreads();
    if (w == 0) {
        s  = (l < 8) ? sh1[l] : 0.f;
        s2 = (l < 8) ? sh2[l] : 0.f;
        for (int off = 4; off; off >>= 1) {
            s  += __shfl_xor_sync(0xffffffffu, s, off);
            s2 += __shfl_xor_sync(0xffffffffu, s2, off);
        }
        if (!l) { sh1[0] = s; sh2[0] = s2; }
    }
    __syncthreads();
    float mu  = sh1[0] * (1.f / DIM_);
    float var = sh2[0] * (1.f / DIM_) - mu * mu;
    float inv = rsqrtf(var + 1e-5f);
#pragma unroll
    for (int i = 0; i < 4; i++) {
        int j = tid + i * 256;
        out[(size_t)t * DIM_ + j] = (v[i] - mu) * inv * g[j] + bb[j];
    }
}

// ===================== launch =====================
extern "C" void kernel_launch(void* const* d_in, const int* in_sizes, int n_in,
                              void* d_out, int out_size)
{
    const float* x        = (const float*)d_in[0];
    const float* in_proj  = (const float*)d_in[1];
    const float* conv_w   = (const float*)d_in[2];
    const float* conv_b   = (const float*)d_in[3];
    const float* xproj_w  = (const float*)d_in[4];
    const float* dtproj_w = (const float*)d_in[5];
    const float* dtproj_b = (const float*)d_in[6];
    const float* D_param  = (const float*)d_in[7];
    const float* sw       = (const float*)d_in[8];
    const float* gate_w1  = (const float*)d_in[9];
    const float* gate_w2  = (const float*)d_in[10];
    const float* out_proj = (const float*)d_in[11];
    const float* ln_g     = (const float*)d_in[12];
    const float* ln_b     = (const float*)d_in[13];
    float* out = (float*)d_out;

    float *xz, *xcA, *projA, *dtA, *o0, *o1, *o2, *fused, *scr;
    __half *x2, *wi2, *gw1b, *gw2b, *wob, *ctx2, *g1b, *u2;
    cudaGetSymbolAddress((void**)&xz,    g_xz);
    cudaGetSymbolAddress((void**)&xcA,   g_xcA);
    cudaGetSymbolAddress((void**)&projA, g_projA);
    cudaGetSymbolAddress((void**)&dtA,   g_dtA);
    cudaGetSymbolAddress((void**)&o0,    g_out0);
    cudaGetSymbolAddress((void**)&o1,    g_out1);
    cudaGetSymbolAddress((void**)&o2,    g_out2);
    cudaGetSymbolAddress((void**)&fused, g_fused);
    cudaGetSymbolAddress((void**)&scr,   g_scr);
    cudaGetSymbolAddress((void**)&x2,    g_x2);
    cudaGetSymbolAddress((void**)&wi2,   g_wi2);
    cudaGetSymbolAddress((void**)&gw1b,  g_gw1b);
    cudaGetSymbolAddress((void**)&gw2b,  g_gw2b);
    cudaGetSymbolAddress((void**)&wob,   g_wob);
    cudaGetSymbolAddress((void**)&ctx2,  g_ctx2);
    cudaGetSymbolAddress((void**)&g1b,   g_g1b);
    cudaGetSymbolAddress((void**)&u2,    g_u2);

    cudaFuncSetAttribute(gemm_fp16, cudaFuncAttributeMaxDynamicSharedMemorySize, GSMEM_BYTES);

    // hi/lo conversions: x (A-mode [hi|lo]), weights (B-mode [hi|hi])
    cvt_kernel<<<(1024 * 1024) / 256, 256>>>(x,        x2,   10, 1);
    cvt_kernel<<<(4096 * 1024) / 256, 256>>>(in_proj,  wi2,  10, 0);
    cvt_kernel<<<(1024 * 2048) / 256, 256>>>(gate_w1,  gw1b, 11, 0);
    cvt_kernel<<<(2048 * 1024) / 256, 256>>>(gate_w2,  gw2b, 10, 0);
    cvt_kernel<<<(1024 * 2048) / 256, 256>>>(out_proj, wob,  11, 0);

    // in_proj: xz[1024,4096] = x @ in_proj_w.T   (Kpair=2048)
    gemm_fp16<<<dim3(32, 8, 1), 128, GSMEM_BYTES>>>(x2, wi2, 2048, 2048, xz, 4096, 0,
                                                    nullptr, 0, nullptr, nullptr, 0);

    // merged per-scale pipeline (all 3 scales per launch)
    conv_silu_all<<<(T_ALL * DI) / 256, 256>>>(xz, conv_w, conv_b, xcA);
    xproj_all<<<T_ALL, 256>>>(xcA, xproj_w, projA);
    dtproj_all<<<(T_ALL * DI) / 256, 256>>>(projA, dtproj_w, dtproj_b, dtA);
    scan_all<<<384, 256>>>(dtA, projA, xcA, D_param, o0, o1, o2);

    fuse_kernel<<<(T_LEN * DI) / 256, 256>>>(o0, o1, o2, sw, fused, ctx2);

    // gate1: split-K x2 (2K=4096 -> 2x2048), partials to scr, combine = silu+pair
    gemm_fp16<<<dim3(8, 8, 2), 128, GSMEM_BYTES>>>(ctx2, gw1b, 2048, 4096,
                                                   scr, DIM_, (size_t)T_LEN * DIM_,
                                                   nullptr, 0, nullptr, nullptr, 0);
    comb_silu_pair<<<(T_LEN * DIM_) / 256, 256>>>(scr, scr + T_LEN * DIM_, g1b);

    // gate2: u = fused * sigmoid(g1 @ gate_w2.T) * silu(gate) -> fp16 pair (K=2048)
    gemm_fp16<<<dim3(16, 8, 1), 128, GSMEM_BYTES>>>(g1b, gw2b, 2048, 2048,
                                                    nullptr, 0, 0,
                                                    u2, 2048, fused, xz, 2);

    // out_proj: split-K x2, partials to scr; combine fused into LayerNorm
    gemm_fp16<<<dim3(8, 8, 2), 128, GSMEM_BYTES>>>(u2, wob, 2048, 4096,
                                                   scr, DIM_, (size_t)T_LEN * DIM_,
                                                   nullptr, 0, nullptr, nullptr, 0);

    ln_kernel<<<T_LEN, 256>>>(scr, scr + T_LEN * DIM_, x, ln_g, ln_b, out);
}

// round 14
// speedup vs baseline: 2.9046x; 1.1981x over previous
#include <cuda_runtime.h>
#include <cuda_fp16.h>
#include <cstdint>
#include <math.h>

#define T_LEN 1024
#define DIM_  1024
#define DI    2048
#define DS    16

// ===================== PTX helpers (family-target safe: no tcgen05) ============
__device__ __forceinline__ uint32_t smem_u32(const void* p) {
    uint32_t a;
    asm("{ .reg .u64 t; cvta.to.shared.u64 t, %1; cvt.u32.u64 %0, t; }" : "=r"(a) : "l"(p));
    return a;
}
#define CP_ASYNC16(dst, src) \
    asm volatile("cp.async.cg.shared.global [%0], [%1], 16;" :: "r"(dst), "l"(src))
#define CP_COMMIT() asm volatile("cp.async.commit_group;")
#define CP_WAIT1()  asm volatile("cp.async.wait_group 1;")
#define CP_WAIT0()  asm volatile("cp.async.wait_group 0;")

#define LDSM_X4(r0, r1, r2, r3, addr) \
    asm volatile("ldmatrix.sync.aligned.m8n8.x4.shared.b16 {%0,%1,%2,%3}, [%4];" \
                 : "=r"(r0), "=r"(r1), "=r"(r2), "=r"(r3) : "r"(addr))

#define MMA16816(c, a, b) \
    asm volatile("mma.sync.aligned.m16n8k16.row.col.f32.f16.f16.f32 " \
                 "{%0,%1,%2,%3},{%4,%5,%6,%7},{%8,%9},{%0,%1,%2,%3};" \
                 : "+f"((c)[0]), "+f"((c)[1]), "+f"((c)[2]), "+f"((c)[3]) \
                 : "r"((a)[0]), "r"((a)[1]), "r"((a)[2]), "r"((a)[3]), \
                   "r"((b)[0]), "r"((b)[1]))

static __device__ __forceinline__ uint32_t swz128(uint32_t off) {
    return off ^ ((off >> 3) & 0x70);
}

// ===================== scratch =====================
#define T_ALL 1792   // 1024 + 512 + 256
__device__ float g_xz[T_LEN * 4096];
__device__ float g_xcA[T_ALL * DI];
__device__ float g_projA[T_ALL * 32];
__device__ float g_dtA[T_ALL * DI];
__device__ float g_out0[T_LEN * DI];
__device__ float g_out1[(T_LEN / 2) * DI];
__device__ float g_out2[(T_LEN / 4) * DI];
__device__ float g_fused[T_LEN * DI];
__device__ float g_scr[2 * T_LEN * DIM_];   // split-K fp32 partials
// fp16 hi/lo paired operand buffers (A: [hi|lo], B: [hi|hi])
__device__ __half g_x2[1024 * 2048];
__device__ __half g_wi2[4096 * 2048];
__device__ __half g_gw1b[1024 * 4096];
__device__ __half g_gw2b[2048 * 2048];
__device__ __half g_wob[1024 * 4096];
__device__ __half g_ctx2[1024 * 4096];
__device__ __half g_g1b[1024 * 2048];
__device__ __half g_u2[1024 * 4096];

// ===================== math helpers =====================
__device__ __forceinline__ float sigmoidf_(float x) { return 1.f / (1.f + __expf(-x)); }
__device__ __forceinline__ float siluf_(float x)    { return x * sigmoidf_(x); }
__device__ __forceinline__ float softplusf_(float x) {
    if (x > 20.f) return x;
    return log1pf(__expf(x));
}

// per-scale row offsets into the concatenated [T_ALL, DI] buffers
__device__ __forceinline__ int scale_of_row(int tg) { return (tg < 1024) ? 0 : (tg < 1536 ? 1 : 2); }
__device__ __forceinline__ int scale_row_base(int s) { return (s == 0) ? 0 : (s == 1 ? 1024 : 1536); }

// ===================== fp32 -> fp16 hi/lo pair converters =====================
// modeA: [hi | lo], modeB: [hi | hi]
__global__ void cvt_kernel(const float* __restrict__ src, __half* __restrict__ dst,
                           int kshift, int modeA)
{
    int i = blockIdx.x * 256 + threadIdx.x;
    int K = 1 << kshift;
    int r = i >> kshift;
    int k = i & (K - 1);
    float v = src[i];
    __half hi = __float2half(v);
    __half lo = __float2half(v - __half2float(hi));
    size_t base = (size_t)r * 2 * K;
    dst[base + k] = hi;
    dst[base + K + k] = modeA ? lo : hi;
}

// ===================== HMMA fp16 GEMM (3-stage pipeline) =====================
// 128x128 CTA tile, BK=64, 4 warps (2x2), warp tile 64x64, 3-stage cp.async.
// C[m,n] = sum_k A[m,k]*B[n,k]; operands K-paired hi/lo fp16 (A=[hi|lo], B=[hi|hi]).
// blockIdx.z slices K (A/B advance z*Kp, C advances z*czstride).
// mode 0: C = acc (fp32); mode 2: fused*sigmoid(acc)*silu(gate) -> fp16 A-pair
#define GSMEM_BYTES 98304   // 3 stages x (16KB A + 16KB B); epilogue staging 66KB fits

__device__ __forceinline__ void load_chunk(const __half* gA, const __half* gB,
                                           int Kstride, int c, uint32_t smA, uint32_t smB,
                                           int tid)
{
    const __half* a0 = gA + c * 64;
    const __half* b0 = gB + c * 64;
#pragma unroll
    for (int s = 0; s < 8; s++) {
        int e = s * 128 + tid;
        int row = e >> 3, seg = e & 7;
        CP_ASYNC16(smA + swz128(row * 128 + seg * 16), a0 + (size_t)row * Kstride + seg * 8);
    }
#pragma unroll
    for (int s = 0; s < 8; s++) {
        int e = s * 128 + tid;
        int row = e >> 3, seg = e & 7;
        CP_ASYNC16(smB + swz128(row * 128 + seg * 16), b0 + (size_t)row * Kstride + seg * 8);
    }
}

__device__ __forceinline__ void store_pair2(__half* rowp, int K, int col, float a, float b)
{
    __half ha = __float2half(a), hb = __float2half(b);
    __half la = __float2half(a - __half2float(ha));
    __half lb = __float2half(b - __half2float(hb));
    __half2 h2; h2.x = ha; h2.y = hb;
    __half2 l2; l2.x = la; l2.y = lb;
    *reinterpret_cast<__half2*>(rowp + col) = h2;
    *reinterpret_cast<__half2*>(rowp + K + col) = l2;
}

__global__ void __launch_bounds__(128) gemm_fp16(
    const __half* __restrict__ A,
    const __half* __restrict__ B,
    int Kp, int Kstride,
    float* __restrict__ C, int ldc, size_t czstride,
    __half* __restrict__ Cb, int Kpair,
    const float* __restrict__ fused, const float* __restrict__ xz,
    int mode)
{
    extern __shared__ char smem[];
    uint32_t sb = smem_u32(smem);
    const int tid = threadIdx.x, wid = tid >> 5, lane = tid & 31;
    const int wm = wid & 1, wn = wid >> 1;   // warp tile 64x64 at (wm*64, wn*64)

    const int bm = blockIdx.y << 7, bn = blockIdx.x << 7;
    const int kz = blockIdx.z;
    const __half* gA = A + (size_t)bm * Kstride + (size_t)kz * Kp;
    const __half* gB = B + (size_t)bn * Kstride + (size_t)kz * Kp;
    C += (size_t)kz * czstride;
    const int NC = Kp >> 6;

    float acc[4][8][4];
#pragma unroll
    for (int mi = 0; mi < 4; mi++)
#pragma unroll
        for (int ni = 0; ni < 8; ni++)
#pragma unroll
            for (int q = 0; q < 4; q++) acc[mi][ni][q] = 0.f;

    const int a_row = wm * 64 + (lane & 7) + ((lane >> 3) & 1) * 8;  // + mi*16
    const int a_kh  = lane >> 4;
    const int b_row = wn * 64 + (lane & 7) + (lane >> 4) * 8;        // + nh*16
    const int b_kh  = (lane >> 3) & 1;

    // prologue: stages 0 and 1
    load_chunk(gA, gB, Kstride, 0, sb, sb + 16384, tid);
    CP_COMMIT();
    if (NC > 1) {
        load_chunk(gA, gB, Kstride, 1, sb + 32768, sb + 49152, tid);
        CP_COMMIT();
    }

    for (int c = 0; c < NC; c++) {
        if (c + 1 < NC) { CP_WAIT1(); } else { CP_WAIT0(); }
        __syncthreads();
        if (c + 2 < NC) {
            uint32_t so = sb + ((c + 2) % 3) * 32768;
            load_chunk(gA, gB, Kstride, c + 2, so, so + 16384, tid);
            CP_COMMIT();
        }

        const uint32_t st = sb + (c % 3) * 32768;
        const uint32_t ab = st, bb = st + 16384;
#pragma unroll
        for (int ks = 0; ks < 4; ks++) {
            uint32_t aF[4][4];
#pragma unroll
            for (int mi = 0; mi < 4; mi++) {
                uint32_t ad = ab + swz128((uint32_t)(a_row + mi * 16) * 128 +
                                          (uint32_t)(ks * 2 + a_kh) * 16);
                LDSM_X4(aF[mi][0], aF[mi][1], aF[mi][2], aF[mi][3], ad);
            }
            uint32_t bF[8][2];
#pragma unroll
            for (int nh = 0; nh < 4; nh++) {
                uint32_t r0, r1, r2, r3;
                uint32_t bd = bb + swz128((uint32_t)(b_row + nh * 16) * 128 +
                                          (uint32_t)(ks * 2 + b_kh) * 16);
                LDSM_X4(r0, r1, r2, r3, bd);
                bF[nh * 2][0] = r0; bF[nh * 2][1] = r1;
                bF[nh * 2 + 1][0] = r2; bF[nh * 2 + 1][1] = r3;
            }
#pragma unroll
            for (int mi = 0; mi < 4; mi++)
#pragma unroll
                for (int ni = 0; ni < 8; ni++)
                    MMA16816(acc[mi][ni], aF[mi], bF[ni]);
        }
    }
    __syncthreads();   // all compute done before smem reuse for staging

    // stage accumulators through SMEM (stride 129 -> conflict-light)
    float* cs = (float*)smem;
#pragma unroll
    for (int mi = 0; mi < 4; mi++) {
        int r0 = wm * 64 + mi * 16 + (lane >> 2);
#pragma unroll
        for (int ni = 0; ni < 8; ni++) {
            int col = wn * 64 + ni * 8 + (lane & 3) * 2;
            cs[r0 * 129 + col]           = acc[mi][ni][0];
            cs[r0 * 129 + col + 1]       = acc[mi][ni][1];
            cs[(r0 + 8) * 129 + col]     = acc[mi][ni][2];
            cs[(r0 + 8) * 129 + col + 1] = acc[mi][ni][3];
        }
    }
    __syncthreads();

    const int m = bm + tid;
    const float* crow = cs + tid * 129;
    if (mode == 0) {
        float* orow = C + (size_t)m * ldc + bn;
#pragma unroll 8
        for (int kk = 0; kk < 32; kk++) {
            float4 v = make_float4(crow[kk * 4], crow[kk * 4 + 1],
                                   crow[kk * 4 + 2], crow[kk * 4 + 3]);
            *reinterpret_cast<float4*>(orow + kk * 4) = v;
        }
    } else {
        __half* orow = Cb + (size_t)m * 2 * Kpair + bn;
        const float* frow = fused + (size_t)m * 2048 + bn;
        const float* grow = xz + (size_t)m * 4096 + 2048 + bn;
#pragma unroll 8
        for (int kk = 0; kk < 64; kk++) {
            float a = frow[kk * 2]     * sigmoidf_(crow[kk * 2])     * siluf_(grow[kk * 2]);
            float b = frow[kk * 2 + 1] * sigmoidf_(crow[kk * 2 + 1]) * siluf_(grow[kk * 2 + 1]);
            store_pair2(orow, Kpair, kk * 2, a, b);
        }
    }
}

// ===================== split-K combiner (gate1) =====================
__global__ void comb_silu_pair(const float* __restrict__ p0,
                               const float* __restrict__ p1,
                               __half* __restrict__ g1b)
{
    int i = blockIdx.x * 256 + threadIdx.x;
    if (i >= T_LEN * DIM_) return;
    int m = i >> 10, k = i & 1023;
    float v = siluf_(p0[i] + p1[i]);
    __half hi = __float2half(v);
    __half lo = __float2half(v - __half2float(hi));
    __half* rowp = g1b + (size_t)m * 2048;
    rowp[k] = hi;
    rowp[1024 + k] = lo;
}

// ===================== merged per-scale kernels =====================
__global__ void conv_silu_all(const float* __restrict__ xz,
                              const float* __restrict__ conv_w,
                              const float* __restrict__ conv_b,
                              float* __restrict__ xcA)
{
    int idx = blockIdx.x * blockDim.x + threadIdx.x;
    if (idx >= T_ALL * DI) return;
    int tg = idx >> 11;
    int d = idx & (DI - 1);
    int s = scale_of_row(tg);
    int t = tg - scale_row_base(s);
    int stride = 1 << s;
    const float* cw = conv_w + s * DI * 4;
    float4 w4 = *reinterpret_cast<const float4*>(cw + d * 4);
    float wk[4] = {w4.x, w4.y, w4.z, w4.w};
    float acc = conv_b[s * DI + d];
    float inv = 1.f / (float)stride;
#pragma unroll
    for (int k = 0; k < 4; k++) {
        int tt = t - 3 + k;
        if (tt >= 0) {
            float v = 0.f;
            int base = tt * stride;
            for (int r = 0; r < stride; r++) v += xz[(size_t)(base + r) * 4096 + d];
            acc += wk[k] * (v * inv);
        }
    }
    xcA[idx] = siluf_(acc);
}

// xproj v2: block = 8 t-rows (same scale), smem-staged xc; each warp carries
// 4 W-rows, reusing every W read across 8 rows and every smem read across 4 j's.
__global__ void __launch_bounds__(256) xproj_v2(const float* __restrict__ xcA,
                                                const float* __restrict__ xproj_w,
                                                float* __restrict__ projA)
{
    extern __shared__ float sxc[];   // 8 * 2048 floats = 64KB
    int tg0 = blockIdx.x * 8;
    int s = scale_of_row(tg0);
    const float* W = xproj_w + s * 32 * DI;
    for (int i = threadIdx.x; i < 8 * 2048; i += 256)
        sxc[i] = xcA[(size_t)tg0 * DI + i];
    __syncthreads();

    int warp = threadIdx.x >> 5, lane = threadIdx.x & 31;
    const float4* s4 = (const float4*)sxc;
    const float4* w40 = (const float4*)(W + (size_t)(warp)      * DI);
    const float4* w41 = (const float4*)(W + (size_t)(warp + 8)  * DI);
    const float4* w42 = (const float4*)(W + (size_t)(warp + 16) * DI);
    const float4* w43 = (const float4*)(W + (size_t)(warp + 24) * DI);

    float acc[4][8];
#pragma unroll
    for (int j = 0; j < 4; j++)
#pragma unroll
        for (int r = 0; r < 8; r++) acc[j][r] = 0.f;

    for (int k = 0; k < 16; k++) {
        int i4 = lane + k * 32;
        float4 wv0 = w40[i4], wv1 = w41[i4], wv2 = w42[i4], wv3 = w43[i4];
#pragma unroll
        for (int r = 0; r < 8; r++) {
            float4 xv = s4[r * 512 + i4];
            acc[0][r] += xv.x * wv0.x + xv.y * wv0.y + xv.z * wv0.z + xv.w * wv0.w;
            acc[1][r] += xv.x * wv1.x + xv.y * wv1.y + xv.z * wv1.z + xv.w * wv1.w;
            acc[2][r] += xv.x * wv2.x + xv.y * wv2.y + xv.z * wv2.z + xv.w * wv2.w;
            acc[3][r] += xv.x * wv3.x + xv.y * wv3.y + xv.z * wv3.z + xv.w * wv3.w;
        }
    }
#pragma unroll
    for (int off = 16; off; off >>= 1)
#pragma unroll
        for (int j = 0; j < 4; j++)
#pragma unroll
            for (int r = 0; r < 8; r++)
                acc[j][r] += __shfl_xor_sync(0xffffffffu, acc[j][r], off);
    if (lane == 0) {
#pragma unroll
        for (int j = 0; j < 4; j++)
#pragma unroll
            for (int r = 0; r < 8; r++)
                projA[(tg0 + r) * 32 + (j * 8 + warp)] = acc[j][r];
    }
}

// dtproj v2: block = (64 t-rows, 256 d); dtw in registers, reused over 64 t.
__global__ void __launch_bounds__(256) dtproj_v2(const float* __restrict__ projA,
                                                 const float* __restrict__ dtw,
                                                 const float* __restrict__ dtb,
                                                 float* __restrict__ dtA)
{
    __shared__ float sp[64 * 16];
    int tc = blockIdx.x >> 3, dc = blockIdx.x & 7;
    int row0 = tc * 64;
    int s = scale_of_row(row0);
    int d = dc * 256 + threadIdx.x;

    for (int i = threadIdx.x; i < 64 * 16; i += 256) {
        int r = i >> 4, c = i & 15;
        sp[i] = projA[(row0 + r) * 32 + c];
    }
    __syncthreads();

    const float4* w4 = (const float4*)(dtw + (size_t)(s * DI + d) * 16);
    float4 w0 = w4[0], w1 = w4[1], w2 = w4[2], w3 = w4[3];
    float bias = dtb[s * DI + d];
    for (int t = 0; t < 64; t++) {
        const float* bp = sp + t * 16;
        float acc = bias;
        acc += bp[0]  * w0.x + bp[1]  * w0.y + bp[2]  * w0.z + bp[3]  * w0.w;
        acc += bp[4]  * w1.x + bp[5]  * w1.y + bp[6]  * w1.z + bp[7]  * w1.w;
        acc += bp[8]  * w2.x + bp[9]  * w2.y + bp[10] * w2.z + bp[11] * w2.w;
        acc += bp[12] * w3.x + bp[13] * w3.y + bp[14] * w3.z + bp[15] * w3.w;
        dtA[(size_t)(row0 + t) * DI + d] = softplusf_(softplusf_(acc));
    }
}

// selective scan, all scales in one launch (384 blocks), unroll x8
__global__ void scan_all(const float* __restrict__ dtA,
                         const float* __restrict__ projA,
                         const float* __restrict__ xcA,
                         const float* __restrict__ D_param,
                         float* __restrict__ y0,
                         float* __restrict__ y1,
                         float* __restrict__ y2)
{
    int s = blockIdx.x >> 7;
    int gid = (blockIdx.x & 127) * 256 + threadIdx.x;
    int n = gid & 15;
    int d = gid >> 4;
    int T = T_LEN >> s;
    int rb = scale_row_base(s);
    const float* dt   = dtA   + (size_t)rb * DI;
    const float* xc   = xcA   + (size_t)rb * DI;
    const float* proj = projA + rb * 32;
    float* y = (s == 0) ? y0 : (s == 1 ? y1 : y2);
    float An = -(float)(n + 1);
    float Dpd = D_param[s * DI + d];
    float h = 0.f;
    for (int t = 0; t < T; t += 8) {
        float v[8], xcs[8];
#pragma unroll
        for (int q = 0; q < 8; q++) {
            int tt = t + q;
            float dtv = dt[(size_t)tt * DI + d];
            float xcv = xc[(size_t)tt * DI + d];
            float Bv  = proj[tt * 32 + n];
            float Cv  = proj[tt * 32 + 16 + n];
            float dA  = fmaxf(__expf(dtv * An), 1e-38f);
            float dBx = fmaxf(dtv * Bv * xcv, 1e-38f);
            h = dA * h + dBx;
            v[q] = Cv * h;
            xcs[q] = xcv;
        }
#pragma unroll
        for (int off = 8; off; off >>= 1) {
#pragma unroll
            for (int q = 0; q < 8; q++)
                v[q] += __shfl_xor_sync(0xffffffffu, v[q], off);
        }
        if (n == 0) {
#pragma unroll
            for (int q = 0; q < 8; q++)
                y[(size_t)(t + q) * DI + d] = v[q] + Dpd * xcs[q];
        }
    }
}

__device__ __forceinline__ float upsample_read(const float* __restrict__ y,
                                               int Tin, int t, int d)
{
    if (Tin == T_LEN) return y[(size_t)t * DI + d];
    float scale = (float)Tin / (float)T_LEN;
    float pos = ((float)t + 0.5f) * scale - 0.5f;
    pos = fminf(fmaxf(pos, 0.f), (float)(Tin - 1));
    int lo = (int)floorf(pos);
    int hi = min(lo + 1, Tin - 1);
    float w = pos - (float)lo;
    return y[(size_t)lo * DI + d] * (1.f - w) + y[(size_t)hi * DI + d] * w;
}

// fused (fp32) + ctx as fp16 A-pair (K=2048) for the gate1 GEMM
__global__ void fuse_kernel(const float* __restrict__ y0,
                            const float* __restrict__ y1,
                            const float* __restrict__ y2,
                            const float* __restrict__ sw,
                            float* __restrict__ fused,
                            __half* __restrict__ ctx2)
{
    int idx = blockIdx.x * blockDim.x + threadIdx.x;
    if (idx >= T_LEN * DI) return;
    int t = idx >> 11, d = idx & (DI - 1);
    float w0 = sw[0], w1 = sw[1], w2 = sw[2];
    float m = fmaxf(w0, fmaxf(w1, w2));
    float e0 = __expf(w0 - m), e1 = __expf(w1 - m), e2 = __expf(w2 - m);
    float inv = 1.f / (e0 + e1 + e2);
    float u0 = y0[idx];
    float u1 = upsample_read(y1, T_LEN / 2, t, d);
    float u2 = upsample_read(y2, T_LEN / 4, t, d);
    fused[idx] = (e0 * u0 + e1 * u1 + e2 * u2) * inv;
    float v = (u0 + u1 + u2) * (1.f / 3.f);
    __half hi = __float2half(v);
    __half lo = __float2half(v - __half2float(hi));
    size_t base = (size_t)t * 4096;
    ctx2[base + d] = hi;
    ctx2[base + 2048 + d] = lo;
}

// residual + LayerNorm, fused with out_proj split-K combine: y = p0 + p1 + x
__global__ void ln_kernel(const float* __restrict__ p0,
                          const float* __restrict__ p1,
                          const float* __restrict__ x,
                          const float* __restrict__ g,
                          const float* __restrict__ bb,
                          float* __restrict__ out)
{
    int t = blockIdx.x;
    int tid = threadIdx.x;
    float v[4];
    float s = 0.f, s2 = 0.f;
#pragma unroll
    for (int i = 0; i < 4; i++) {
        int j = tid + i * 256;
        size_t off = (size_t)t * DIM_ + j;
        float y = p0[off] + p1[off] + x[off];
        v[i] = y; s += y; s2 += y * y;
    }
    __shared__ float sh1[8], sh2[8];
    for (int off = 16; off; off >>= 1) {
        s  += __shfl_xor_sync(0xffffffffu, s, off);
        s2 += __shfl_xor_sync(0xffffffffu, s2, off);
    }
    int w = tid >> 5, l = tid & 31;
    if (!l) { sh1[w] = s; sh2[w] = s2; }
    __syncthreads();
    if (w == 0) {
        s  = (l < 8) ? sh1[l] : 0.f;
        s2 = (l < 8) ? sh2[l] : 0.f;
        for (int off = 4; off; off >>= 1) {
            s  += __shfl_xor_sync(0xffffffffu, s, off);
            s2 += __shfl_xor_sync(0xffffffffu, s2, off);
        }
        if (!l) { sh1[0] = s; sh2[0] = s2; }
    }
    __syncthreads();
    float mu  = sh1[0] * (1.f / DIM_);
    float var = sh2[0] * (1.f / DIM_) - mu * mu;
    float inv = rsqrtf(var + 1e-5f);
#pragma unroll
    for (int i = 0; i < 4; i++) {
        int j = tid + i * 256;
        out[(size_t)t * DIM_ + j] = (v[i] - mu) * inv * g[j] + bb[j];
    }
}

// ===================== launch =====================
extern "C" void kernel_launch(void* const* d_in, const int* in_sizes, int n_in,
                              void* d_out, int out_size)
{
    const float* x        = (const float*)d_in[0];
    const float* in_proj  = (const float*)d_in[1];
    const float* conv_w   = (const float*)d_in[2];
    const float* conv_b   = (const float*)d_in[3];
    const float* xproj_w  = (const float*)d_in[4];
    const float* dtproj_w = (const float*)d_in[5];
    const float* dtproj_b = (const float*)d_in[6];
    const float* D_param  = (const float*)d_in[7];
    const float* sw       = (const float*)d_in[8];
    const float* gate_w1  = (const float*)d_in[9];
    const float* gate_w2  = (const float*)d_in[10];
    const float* out_proj = (const float*)d_in[11];
    const float* ln_g     = (const float*)d_in[12];
    const float* ln_b     = (const float*)d_in[13];
    float* out = (float*)d_out;

    float *xz, *xcA, *projA, *dtA, *o0, *o1, *o2, *fused, *scr;
    __half *x2, *wi2, *gw1b, *gw2b, *wob, *ctx2, *g1b, *u2;
    cudaGetSymbolAddress((void**)&xz,    g_xz);
    cudaGetSymbolAddress((void**)&xcA,   g_xcA);
    cudaGetSymbolAddress((void**)&projA, g_projA);
    cudaGetSymbolAddress((void**)&dtA,   g_dtA);
    cudaGetSymbolAddress((void**)&o0,    g_out0);
    cudaGetSymbolAddress((void**)&o1,    g_out1);
    cudaGetSymbolAddress((void**)&o2,    g_out2);
    cudaGetSymbolAddress((void**)&fused, g_fused);
    cudaGetSymbolAddress((void**)&scr,   g_scr);
    cudaGetSymbolAddress((void**)&x2,    g_x2);
    cudaGetSymbolAddress((void**)&wi2,   g_wi2);
    cudaGetSymbolAddress((void**)&gw1b,  g_gw1b);
    cudaGetSymbolAddress((void**)&gw2b,  g_gw2b);
    cudaGetSymbolAddress((void**)&wob,   g_wob);
    cudaGetSymbolAddress((void**)&ctx2,  g_ctx2);
    cudaGetSymbolAddress((void**)&g1b,   g_g1b);
    cudaGetSymbolAddress((void**)&u2,    g_u2);

    cudaFuncSetAttribute(gemm_fp16, cudaFuncAttributeMaxDynamicSharedMemorySize, GSMEM_BYTES);
    cudaFuncSetAttribute(xproj_v2,  cudaFuncAttributeMaxDynamicSharedMemorySize, 65536);

    // hi/lo conversions: x (A-mode [hi|lo]), weights (B-mode [hi|hi])
    cvt_kernel<<<(1024 * 1024) / 256, 256>>>(x,        x2,   10, 1);
    cvt_kernel<<<(4096 * 1024) / 256, 256>>>(in_proj,  wi2,  10, 0);
    cvt_kernel<<<(1024 * 2048) / 256, 256>>>(gate_w1,  gw1b, 11, 0);
    cvt_kernel<<<(2048 * 1024) / 256, 256>>>(gate_w2,  gw2b, 10, 0);
    cvt_kernel<<<(1024 * 2048) / 256, 256>>>(out_proj, wob,  11, 0);

    // in_proj: xz[1024,4096] = x @ in_proj_w.T   (Kpair=2048)
    gemm_fp16<<<dim3(32, 8, 1), 128, GSMEM_BYTES>>>(x2, wi2, 2048, 2048, xz, 4096, 0,
                                                    nullptr, 0, nullptr, nullptr, 0);

    // merged per-scale pipeline (all 3 scales per launch)
    conv_silu_all<<<(T_ALL * DI) / 256, 256>>>(xz, conv_w, conv_b, xcA);
    xproj_v2<<<T_ALL / 8, 256, 65536>>>(xcA, xproj_w, projA);
    dtproj_v2<<<(T_ALL / 64) * 8, 256>>>(projA, dtproj_w, dtproj_b, dtA);
    scan_all<<<384, 256>>>(dtA, projA, xcA, D_param, o0, o1, o2);

    fuse_kernel<<<(T_LEN * DI) / 256, 256>>>(o0, o1, o2, sw, fused, ctx2);

    // gate1: split-K x2 (2K=4096 -> 2x2048), partials to scr, combine = silu+pair
    gemm_fp16<<<dim3(8, 8, 2), 128, GSMEM_BYTES>>>(ctx2, gw1b, 2048, 4096,
                                                   scr, DIM_, (size_t)T_LEN * DIM_,
                                                   nullptr, 0, nullptr, nullptr, 0);
    comb_silu_pair<<<(T_LEN * DIM_) / 256, 256>>>(scr, scr + T_LEN * DIM_, g1b);

    // gate2: u = fused * sigmoid(g1 @ gate_w2.T) * silu(gate) -> fp16 pair (K=2048)
    gemm_fp16<<<dim3(16, 8, 1), 128, GSMEM_BYTES>>>(g1b, gw2b, 2048, 2048,
                                                    nullptr, 0, 0,
                                                    u2, 2048, fused, xz, 2);

    // out_proj: split-K x2, partials to scr; combine fused into LayerNorm
    gemm_fp16<<<dim3(8, 8, 2), 128, GSMEM_BYTES>>>(u2, wob, 2048, 4096,
                                                   scr, DIM_, (size_t)T_LEN * DIM_,
                                                   nullptr, 0, nullptr, nullptr, 0);

    ln_kernel<<<T_LEN, 256>>>(scr, scr + T_LEN * DIM_, x, ln_g, ln_b, out);
}

// round 16
// speedup vs baseline: 3.2509x; 1.1193x over previous
#include <cuda_runtime.h>
#include <cuda_fp16.h>
#include <cstdint>
#include <math.h>

#define T_LEN 1024
#define DIM_  1024
#define DI    2048
#define DS    16

// ===================== PTX helpers (family-target safe: no tcgen05) ============
__device__ __forceinline__ uint32_t smem_u32(const void* p) {
    uint32_t a;
    asm("{ .reg .u64 t; cvta.to.shared.u64 t, %1; cvt.u32.u64 %0, t; }" : "=r"(a) : "l"(p));
    return a;
}
#define CP_ASYNC16(dst, src) \
    asm volatile("cp.async.cg.shared.global [%0], [%1], 16;" :: "r"(dst), "l"(src))
#define CP_COMMIT() asm volatile("cp.async.commit_group;")
#define CP_WAIT1()  asm volatile("cp.async.wait_group 1;")
#define CP_WAIT0()  asm volatile("cp.async.wait_group 0;")

#define LDSM_X4(r0, r1, r2, r3, addr) \
    asm volatile("ldmatrix.sync.aligned.m8n8.x4.shared.b16 {%0,%1,%2,%3}, [%4];" \
                 : "=r"(r0), "=r"(r1), "=r"(r2), "=r"(r3) : "r"(addr))

#define MMA16816(c, a, b) \
    asm volatile("mma.sync.aligned.m16n8k16.row.col.f32.f16.f16.f32 " \
                 "{%0,%1,%2,%3},{%4,%5,%6,%7},{%8,%9},{%0,%1,%2,%3};" \
                 : "+f"((c)[0]), "+f"((c)[1]), "+f"((c)[2]), "+f"((c)[3]) \
                 : "r"((a)[0]), "r"((a)[1]), "r"((a)[2]), "r"((a)[3]), \
                   "r"((b)[0]), "r"((b)[1]))

static __device__ __forceinline__ uint32_t swz128(uint32_t off) {
    return off ^ ((off >> 3) & 0x70);
}

// ===================== scratch =====================
#define T_ALL 1792   // 1024 + 512 + 256
__device__ float g_xz[T_LEN * 4096];
__device__ float g_xcA[T_ALL * DI];
__device__ float g_projA[T_ALL * 32];
__device__ float g_dtA[T_ALL * DI];
__device__ float g_out0[T_LEN * DI];
__device__ float g_out1[(T_LEN / 2) * DI];
__device__ float g_out2[(T_LEN / 4) * DI];
__device__ float g_fused[T_LEN * DI];
__device__ float g_scr[2 * T_LEN * DIM_];   // split-K fp32 partials
// fp16 operand buffers. A-side: [hi|lo] pairs. B-side: single hi copy.
__device__ __half g_x2[1024 * 2048];       // A pair, Kp=2048
__device__ __half g_wi2[4096 * 1024];      // B single
__device__ __half g_gw1b[1024 * 2048];     // B single
__device__ __half g_gw2b[2048 * 1024];     // B single
__device__ __half g_wob[1024 * 2048];      // B single
__device__ __half g_ctx2[1024 * 4096];     // A pair, 2x2048
__device__ __half g_g1b[1024 * 1024];      // A hi-only (gate2)
__device__ __half g_u2[1024 * 4096];       // A pair, 2x2048

// ===================== math helpers =====================
__device__ __forceinline__ float sigmoidf_(float x) { return 1.f / (1.f + __expf(-x)); }
__device__ __forceinline__ float siluf_(float x)    { return x * sigmoidf_(x); }
__device__ __forceinline__ float softplusf_(float x) {
    if (x > 20.f) return x;
    return log1pf(__expf(x));
}

// per-scale row offsets into the concatenated [T_ALL, DI] buffers
__device__ __forceinline__ int scale_of_row(int tg) { return (tg < 1024) ? 0 : (tg < 1536 ? 1 : 2); }
__device__ __forceinline__ int scale_row_base(int s) { return (s == 0) ? 0 : (s == 1 ? 1024 : 1536); }

// ===================== converters =====================
// A-side: fp32 -> fp16 [hi | lo] pair rows
__global__ void cvt_pairA(const float* __restrict__ src, __half* __restrict__ dst,
                          int kshift)
{
    int i = blockIdx.x * 256 + threadIdx.x;
    int K = 1 << kshift;
    int r = i >> kshift;
    int k = i & (K - 1);
    float v = src[i];
    __half hi = __float2half(v);
    __half lo = __float2half(v - __half2float(hi));
    size_t base = (size_t)r * 2 * K;
    dst[base + k] = hi;
    dst[base + K + k] = lo;
}

// B-side: plain fp32 -> fp16 cast, 4 tensors in one launch, float4-vectorized
__global__ void cvt_cast4(const float* __restrict__ s0, __half* __restrict__ d0, int n0,
                          const float* __restrict__ s1, __half* __restrict__ d1, int n1,
                          const float* __restrict__ s2, __half* __restrict__ d2, int n2,
                          const float* __restrict__ s3, __half* __restrict__ d3, int n3)
{
    int q = blockIdx.x * 256 + threadIdx.x;   // quad index
    const float* s; __half* d; int base;
    if      (q < n0)               { s = s0; d = d0; base = q; }
    else if (q < n0 + n1)          { s = s1; d = d1; base = q - n0; }
    else if (q < n0 + n1 + n2)     { s = s2; d = d2; base = q - n0 - n1; }
    else if (q < n0 + n1 + n2 + n3){ s = s3; d = d3; base = q - n0 - n1 - n2; }
    else return;
    float4 v = reinterpret_cast<const float4*>(s)[base];
    __half2 h0; h0.x = __float2half(v.x); h0.y = __float2half(v.y);
    __half2 h1; h1.x = __float2half(v.z); h1.y = __float2half(v.w);
    reinterpret_cast<__half2*>(d)[base * 2]     = h0;
    reinterpret_cast<__half2*>(d)[base * 2 + 1] = h1;
}

// ===================== HMMA fp16 GEMM (3-stage pipeline, wrapped B) ===========
// 128x128 CTA tile, BK=64, 4 warps (2x2), warp tile 64x64, 3-stage cp.async.
// C[m,n] = sum_k A[m,k]*B[n,k]; A K-walked over Kp (usually [hi|lo] pair),
// B single-width: chunk index wraps via (c & cmask); kz never advances B.
// mode 0: C = acc (fp32); mode 2: fused*sigmoid(acc)*silu(gate) -> fp16 A-pair
#define GSMEM_BYTES 98304

__device__ __forceinline__ void load_chunk(const __half* gA, int KsA, int cA,
                                           const __half* gB, int KsB, int cB,
                                           uint32_t smA, uint32_t smB, int tid)
{
    const __half* a0 = gA + cA * 64;
    const __half* b0 = gB + cB * 64;
#pragma unroll
    for (int s = 0; s < 8; s++) {
        int e = s * 128 + tid;
        int row = e >> 3, seg = e & 7;
        CP_ASYNC16(smA + swz128(row * 128 + seg * 16), a0 + (size_t)row * KsA + seg * 8);
    }
#pragma unroll
    for (int s = 0; s < 8; s++) {
        int e = s * 128 + tid;
        int row = e >> 3, seg = e & 7;
        CP_ASYNC16(smB + swz128(row * 128 + seg * 16), b0 + (size_t)row * KsB + seg * 8);
    }
}

__device__ __forceinline__ void store_pair2(__half* rowp, int K, int col, float a, float b)
{
    __half ha = __float2half(a), hb = __float2half(b);
    __half la = __float2half(a - __half2float(ha));
    __half lb = __float2half(b - __half2float(hb));
    __half2 h2; h2.x = ha; h2.y = hb;
    __half2 l2; l2.x = la; l2.y = lb;
    *reinterpret_cast<__half2*>(rowp + col) = h2;
    *reinterpret_cast<__half2*>(rowp + K + col) = l2;
}

__global__ void __launch_bounds__(128) gemm_fp16(
    const __half* __restrict__ A,
    const __half* __restrict__ B,
    int Kp, int KsA, int KsB, int cmask,
    float* __restrict__ C, int ldc, size_t czstride,
    __half* __restrict__ Cb, int Kpair,
    const float* __restrict__ fused, const float* __restrict__ xz,
    int mode)
{
    extern __shared__ char smem[];
    uint32_t sb = smem_u32(smem);
    const int tid = threadIdx.x, wid = tid >> 5, lane = tid & 31;
    const int wm = wid & 1, wn = wid >> 1;   // warp tile 64x64 at (wm*64, wn*64)

    const int bm = blockIdx.y << 7, bn = blockIdx.x << 7;
    const int kz = blockIdx.z;
    const __half* gA = A + (size_t)bm * KsA + (size_t)kz * Kp;
    const __half* gB = B + (size_t)bn * KsB;   // kz does NOT advance B (lo dropped)
    C += (size_t)kz * czstride;
    const int NC = Kp >> 6;

    float acc[4][8][4];
#pragma unroll
    for (int mi = 0; mi < 4; mi++)
#pragma unroll
        for (int ni = 0; ni < 8; ni++)
#pragma unroll
            for (int q = 0; q < 4; q++) acc[mi][ni][q] = 0.f;

    const int a_row = wm * 64 + (lane & 7) + ((lane >> 3) & 1) * 8;  // + mi*16
    const int a_kh  = lane >> 4;
    const int b_row = wn * 64 + (lane & 7) + (lane >> 4) * 8;        // + nh*16
    const int b_kh  = (lane >> 3) & 1;

    // prologue: stages 0 and 1
    load_chunk(gA, KsA, 0, gB, KsB, 0, sb, sb + 16384, tid);
    CP_COMMIT();
    if (NC > 1) {
        load_chunk(gA, KsA, 1, gB, KsB, 1 & cmask, sb + 32768, sb + 49152, tid);
        CP_COMMIT();
    }

    for (int c = 0; c < NC; c++) {
        if (c + 1 < NC) { CP_WAIT1(); } else { CP_WAIT0(); }
        __syncthreads();
        if (c + 2 < NC) {
            uint32_t so = sb + ((c + 2) % 3) * 32768;
            load_chunk(gA, KsA, c + 2, gB, KsB, (c + 2) & cmask, so, so + 16384, tid);
            CP_COMMIT();
        }

        const uint32_t st = sb + (c % 3) * 32768;
        const uint32_t ab = st, bb = st + 16384;
#pragma unroll
        for (int ks = 0; ks < 4; ks++) {
            uint32_t aF[4][4];
#pragma unroll
            for (int mi = 0; mi < 4; mi++) {
                uint32_t ad = ab + swz128((uint32_t)(a_row + mi * 16) * 128 +
                                          (uint32_t)(ks * 2 + a_kh) * 16);
                LDSM_X4(aF[mi][0], aF[mi][1], aF[mi][2], aF[mi][3], ad);
            }
            uint32_t bF[8][2];
#pragma unroll
            for (int nh = 0; nh < 4; nh++) {
                uint32_t r0, r1, r2, r3;
                uint32_t bd = bb + swz128((uint32_t)(b_row + nh * 16) * 128 +
                                          (uint32_t)(ks * 2 + b_kh) * 16);
                LDSM_X4(r0, r1, r2, r3, bd);
                bF[nh * 2][0] = r0; bF[nh * 2][1] = r1;
                bF[nh * 2 + 1][0] = r2; bF[nh * 2 + 1][1] = r3;
            }
#pragma unroll
            for (int mi = 0; mi < 4; mi++)
#pragma unroll
                for (int ni = 0; ni < 8; ni++)
                    MMA16816(acc[mi][ni], aF[mi], bF[ni]);
        }
    }
    __syncthreads();   // all compute done before smem reuse for staging

    // stage accumulators through SMEM (stride 129 -> conflict-light)
    float* cs = (float*)smem;
#pragma unroll
    for (int mi = 0; mi < 4; mi++) {
        int r0 = wm * 64 + mi * 16 + (lane >> 2);
#pragma unroll
        for (int ni = 0; ni < 8; ni++) {
            int col = wn * 64 + ni * 8 + (lane & 3) * 2;
            cs[r0 * 129 + col]           = acc[mi][ni][0];
            cs[r0 * 129 + col + 1]       = acc[mi][ni][1];
            cs[(r0 + 8) * 129 + col]     = acc[mi][ni][2];
            cs[(r0 + 8) * 129 + col + 1] = acc[mi][ni][3];
        }
    }
    __syncthreads();

    const int m = bm + tid;
    const float* crow = cs + tid * 129;
    if (mode == 0) {
        float* orow = C + (size_t)m * ldc + bn;
#pragma unroll 8
        for (int kk = 0; kk < 32; kk++) {
            float4 v = make_float4(crow[kk * 4], crow[kk * 4 + 1],
                                   crow[kk * 4 + 2], crow[kk * 4 + 3]);
            *reinterpret_cast<float4*>(orow + kk * 4) = v;
        }
    } else {
        __half* orow = Cb + (size_t)m * 2 * Kpair + bn;
        const float* frow = fused + (size_t)m * 2048 + bn;
        const float* grow = xz + (size_t)m * 4096 + 2048 + bn;
#pragma unroll 8
        for (int kk = 0; kk < 64; kk++) {
            float a = frow[kk * 2]     * sigmoidf_(crow[kk * 2])     * siluf_(grow[kk * 2]);
            float b = frow[kk * 2 + 1] * sigmoidf_(crow[kk * 2 + 1]) * siluf_(grow[kk * 2 + 1]);
            store_pair2(orow, Kpair, kk * 2, a, b);
        }
    }
}

// ===================== split-K combiner (gate1) =====================
// g1 = silu(p0 + p1) -> fp16 hi-only rows (K=1024) into g1b (gate2 A operand)
__global__ void comb_silu_hi(const float* __restrict__ p0,
                             const float* __restrict__ p1,
                             __half* __restrict__ g1b)
{
    int i = blockIdx.x * 256 + threadIdx.x;
    if (i >= T_LEN * DIM_) return;
    g1b[i] = __float2half(siluf_(p0[i] + p1[i]));
}

// ===================== merged per-scale kernels =====================
__global__ void conv_silu_all(const float* __restrict__ xz,
                              const float* __restrict__ conv_w,
                              const float* __restrict__ conv_b,
                              float* __restrict__ xcA)
{
    int idx = blockIdx.x * blockDim.x + threadIdx.x;
    if (idx >= T_ALL * DI) return;
    int tg = idx >> 11;
    int d = idx & (DI - 1);
    int s = scale_of_row(tg);
    int t = tg - scale_row_base(s);
    int stride = 1 << s;
    const float* cw = conv_w + s * DI * 4;
    float4 w4 = *reinterpret_cast<const float4*>(cw + d * 4);
    float wk[4] = {w4.x, w4.y, w4.z, w4.w};
    float acc = conv_b[s * DI + d];
    float inv = 1.f / (float)stride;
#pragma unroll
    for (int k = 0; k < 4; k++) {
        int tt = t - 3 + k;
        if (tt >= 0) {
            float v = 0.f;
            int base = tt * stride;
            for (int r = 0; r < stride; r++) v += xz[(size_t)(base + r) * 4096 + d];
            acc += wk[k] * (v * inv);
        }
    }
    xcA[idx] = siluf_(acc);
}

// xproj v2: block = 8 t-rows (same scale), smem-staged xc; each warp carries
// 4 W-rows, reusing every W read across 8 rows and every smem read across 4 j's.
__global__ void __launch_bounds__(256) xproj_v2(const float* __restrict__ xcA,
                                                const float* __restrict__ xproj_w,
                                                float* __restrict__ projA)
{
    extern __shared__ float sxc[];   // 8 * 2048 floats = 64KB
    int tg0 = blockIdx.x * 8;
    int s = scale_of_row(tg0);
    const float* W = xproj_w + s * 32 * DI;
    for (int i = threadIdx.x; i < 8 * 2048; i += 256)
        sxc[i] = xcA[(size_t)tg0 * DI + i];
    __syncthreads();

    int warp = threadIdx.x >> 5, lane = threadIdx.x & 31;
    const float4* s4 = (const float4*)sxc;
    const float4* w40 = (const float4*)(W + (size_t)(warp)      * DI);
    const float4* w41 = (const float4*)(W + (size_t)(warp + 8)  * DI);
    const float4* w42 = (const float4*)(W + (size_t)(warp + 16) * DI);
    const float4* w43 = (const float4*)(W + (size_t)(warp + 24) * DI);

    float acc[4][8];
#pragma unroll
    for (int j = 0; j < 4; j++)
#pragma unroll
        for (int r = 0; r < 8; r++) acc[j][r] = 0.f;

    for (int k = 0; k < 16; k++) {
        int i4 = lane + k * 32;
        float4 wv0 = w40[i4], wv1 = w41[i4], wv2 = w42[i4], wv3 = w43[i4];
#pragma unroll
        for (int r = 0; r < 8; r++) {
            float4 xv = s4[r * 512 + i4];
            acc[0][r] += xv.x * wv0.x + xv.y * wv0.y + xv.z * wv0.z + xv.w * wv0.w;
            acc[1][r] += xv.x * wv1.x + xv.y * wv1.y + xv.z * wv1.z + xv.w * wv1.w;
            acc[2][r] += xv.x * wv2.x + xv.y * wv2.y + xv.z * wv2.z + xv.w * wv2.w;
            acc[3][r] += xv.x * wv3.x + xv.y * wv3.y + xv.z * wv3.z + xv.w * wv3.w;
        }
    }
#pragma unroll
    for (int off = 16; off; off >>= 1)
#pragma unroll
        for (int j = 0; j < 4; j++)
#pragma unroll
            for (int r = 0; r < 8; r++)
                acc[j][r] += __shfl_xor_sync(0xffffffffu, acc[j][r], off);
    if (lane == 0) {
#pragma unroll
        for (int j = 0; j < 4; j++)
#pragma unroll
            for (int r = 0; r < 8; r++)
                projA[(tg0 + r) * 32 + (j * 8 + warp)] = acc[j][r];
    }
}

// dtproj v2: block = (64 t-rows, 256 d); dtw in registers, reused over 64 t.
__global__ void __launch_bounds__(256) dtproj_v2(const float* __restrict__ projA,
                                                 const float* __restrict__ dtw,
                                                 const float* __restrict__ dtb,
                                                 float* __restrict__ dtA)
{
    __shared__ float sp[64 * 16];
    int tc = blockIdx.x >> 3, dc = blockIdx.x & 7;
    int row0 = tc * 64;
    int s = scale_of_row(row0);
    int d = dc * 256 + threadIdx.x;

    for (int i = threadIdx.x; i < 64 * 16; i += 256) {
        int r = i >> 4, c = i & 15;
        sp[i] = projA[(row0 + r) * 32 + c];
    }
    __syncthreads();

    const float4* w4 = (const float4*)(dtw + (size_t)(s * DI + d) * 16);
    float4 w0 = w4[0], w1 = w4[1], w2 = w4[2], w3 = w4[3];
    float bias = dtb[s * DI + d];
    for (int t = 0; t < 64; t++) {
        const float* bp = sp + t * 16;
        float acc = bias;
        acc += bp[0]  * w0.x + bp[1]  * w0.y + bp[2]  * w0.z + bp[3]  * w0.w;
        acc += bp[4]  * w1.x + bp[5]  * w1.y + bp[6]  * w1.z + bp[7]  * w1.w;
        acc += bp[8]  * w2.x + bp[9]  * w2.y + bp[10] * w2.z + bp[11] * w2.w;
        acc += bp[12] * w3.x + bp[13] * w3.y + bp[14] * w3.z + bp[15] * w3.w;
        dtA[(size_t)(row0 + t) * DI + d] = softplusf_(softplusf_(acc));
    }
}

// selective scan, all scales in one launch (384 blocks), unroll x8
__global__ void scan_all(const float* __restrict__ dtA,
                         const float* __restrict__ projA,
                         const float* __restrict__ xcA,
                         const float* __restrict__ D_param,
                         float* __restrict__ y0,
                         float* __restrict__ y1,
                         float* __restrict__ y2)
{
    int s = blockIdx.x >> 7;
    int gid = (blockIdx.x & 127) * 256 + threadIdx.x;
    int n = gid & 15;
    int d = gid >> 4;
    int T = T_LEN >> s;
    int rb = scale_row_base(s);
    const float* dt   = dtA   + (size_t)rb * DI;
    const float* xc   = xcA   + (size_t)rb * DI;
    const float* proj = projA + rb * 32;
    float* y = (s == 0) ? y0 : (s == 1 ? y1 : y2);
    float An = -(float)(n + 1);
    float Dpd = D_param[s * DI + d];
    float h = 0.f;
    for (int t = 0; t < T; t += 8) {
        float v[8], xcs[8];
#pragma unroll
        for (int q = 0; q < 8; q++) {
            int tt = t + q;
            float dtv = dt[(size_t)tt * DI + d];
            float xcv = xc[(size_t)tt * DI + d];
            float Bv  = proj[tt * 32 + n];
            float Cv  = proj[tt * 32 + 16 + n];
            float dA  = fmaxf(__expf(dtv * An), 1e-38f);
            float dBx = fmaxf(dtv * Bv * xcv, 1e-38f);
            h = dA * h + dBx;
            v[q] = Cv * h;
            xcs[q] = xcv;
        }
#pragma unroll
        for (int off = 8; off; off >>= 1) {
#pragma unroll
            for (int q = 0; q < 8; q++)
                v[q] += __shfl_xor_sync(0xffffffffu, v[q], off);
        }
        if (n == 0) {
#pragma unroll
            for (int q = 0; q < 8; q++)
                y[(size_t)(t + q) * DI + d] = v[q] + Dpd * xcs[q];
        }
    }
}

__device__ __forceinline__ float upsample_read(const float* __restrict__ y,
                                               int Tin, int t, int d)
{
    if (Tin == T_LEN) return y[(size_t)t * DI + d];
    float scale = (float)Tin / (float)T_LEN;
    float pos = ((float)t + 0.5f) * scale - 0.5f;
    pos = fminf(fmaxf(pos, 0.f), (float)(Tin - 1));
    int lo = (int)floorf(pos);
    int hi = min(lo + 1, Tin - 1);
    float w = pos - (float)lo;
    return y[(size_t)lo * DI + d] * (1.f - w) + y[(size_t)hi * DI + d] * w;
}

// fused (fp32) + ctx as fp16 A-pair (K=2048) for the gate1 GEMM
__global__ void fuse_kernel(const float* __restrict__ y0,
                            const float* __restrict__ y1,
                            const float* __restrict__ y2,
                            const float* __restrict__ sw,
                            float* __restrict__ fused,
                            __half* __restrict__ ctx2)
{
    int idx = blockIdx.x * blockDim.x + threadIdx.x;
    if (idx >= T_LEN * DI) return;
    int t = idx >> 11, d = idx & (DI - 1);
    float w0 = sw[0], w1 = sw[1], w2 = sw[2];
    float m = fmaxf(w0, fmaxf(w1, w2));
    float e0 = __expf(w0 - m), e1 = __expf(w1 - m), e2 = __expf(w2 - m);
    float inv = 1.f / (e0 + e1 + e2);
    float u0 = y0[idx];
    float u1 = upsample_read(y1, T_LEN / 2, t, d);
    float u2 = upsample_read(y2, T_LEN / 4, t, d);
    fused[idx] = (e0 * u0 + e1 * u1 + e2 * u2) * inv;
    float v = (u0 + u1 + u2) * (1.f / 3.f);
    __half hi = __float2half(v);
    __half lo = __float2half(v - __half2float(hi));
    size_t base = (size_t)t * 4096;
    ctx2[base + d] = hi;
    ctx2[base + 2048 + d] = lo;
}

// residual + LayerNorm, fused with out_proj split-K combine: y = p0 + p1 + x
__global__ void ln_kernel(const float* __restrict__ p0,
                          const float* __restrict__ p1,
                          const float* __restrict__ x,
                          const float* __restrict__ g,
                          const float* __restrict__ bb,
                          float* __restrict__ out)
{
    int t = blockIdx.x;
    int tid = threadIdx.x;
    float v[4];
    float s = 0.f, s2 = 0.f;
#pragma unroll
    for (int i = 0; i < 4; i++) {
        int j = tid + i * 256;
        size_t off = (size_t)t * DIM_ + j;
        float y = p0[off] + p1[off] + x[off];
        v[i] = y; s += y; s2 += y * y;
    }
    __shared__ float sh1[8], sh2[8];
    for (int off = 16; off; off >>= 1) {
        s  += __shfl_xor_sync(0xffffffffu, s, off);
        s2 += __shfl_xor_sync(0xffffffffu, s2, off);
    }
    int w = tid >> 5, l = tid & 31;
    if (!l) { sh1[w] = s; sh2[w] = s2; }
    __syncthreads();
    if (w == 0) {
        s  = (l < 8) ? sh1[l] : 0.f;
        s2 = (l < 8) ? sh2[l] : 0.f;
        for (int off = 4; off; off >>= 1) {
            s  += __shfl_xor_sync(0xffffffffu, s, off);
            s2 += __shfl_xor_sync(0xffffffffu, s2, off);
        }
        if (!l) { sh1[0] = s; sh2[0] = s2; }
    }
    __syncthreads();
    float mu  = sh1[0] * (1.f / DIM_);
    float var = sh2[0] * (1.f / DIM_) - mu * mu;
    float inv = rsqrtf(var + 1e-5f);
#pragma unroll
    for (int i = 0; i < 4; i++) {
        int j = tid + i * 256;
        out[(size_t)t * DIM_ + j] = (v[i] - mu) * inv * g[j] + bb[j];
    }
}

// ===================== launch =====================
extern "C" void kernel_launch(void* const* d_in, const int* in_sizes, int n_in,
                              void* d_out, int out_size)
{
    const float* x        = (const float*)d_in[0];
    const float* in_proj  = (const float*)d_in[1];
    const float* conv_w   = (const float*)d_in[2];
    const float* conv_b   = (const float*)d_in[3];
    const float* xproj_w  = (const float*)d_in[4];
    const float* dtproj_w = (const float*)d_in[5];
    const float* dtproj_b = (const float*)d_in[6];
    const float* D_param  = (const float*)d_in[7];
    const float* sw       = (const float*)d_in[8];
    const float* gate_w1  = (const float*)d_in[9];
    const float* gate_w2  = (const float*)d_in[10];
    const float* out_proj = (const float*)d_in[11];
    const float* ln_g     = (const float*)d_in[12];
    const float* ln_b     = (const float*)d_in[13];
    float* out = (float*)d_out;

    float *xz, *xcA, *projA, *dtA, *o0, *o1, *o2, *fused, *scr;
    __half *x2, *wi2, *gw1b, *gw2b, *wob, *ctx2, *g1b, *u2;
    cudaGetSymbolAddress((void**)&xz,    g_xz);
    cudaGetSymbolAddress((void**)&xcA,   g_xcA);
    cudaGetSymbolAddress((void**)&projA, g_projA);
    cudaGetSymbolAddress((void**)&dtA,   g_dtA);
    cudaGetSymbolAddress((void**)&o0,    g_out0);
    cudaGetSymbolAddress((void**)&o1,    g_out1);
    cudaGetSymbolAddress((void**)&o2,    g_out2);
    cudaGetSymbolAddress((void**)&fused, g_fused);
    cudaGetSymbolAddress((void**)&scr,   g_scr);
    cudaGetSymbolAddress((void**)&x2,    g_x2);
    cudaGetSymbolAddress((void**)&wi2,   g_wi2);
    cudaGetSymbolAddress((void**)&gw1b,  g_gw1b);
    cudaGetSymbolAddress((void**)&gw2b,  g_gw2b);
    cudaGetSymbolAddress((void**)&wob,   g_wob);
    cudaGetSymbolAddress((void**)&ctx2,  g_ctx2);
    cudaGetSymbolAddress((void**)&g1b,   g_g1b);
    cudaGetSymbolAddress((void**)&u2,    g_u2);

    cudaFuncSetAttribute(gemm_fp16, cudaFuncAttributeMaxDynamicSharedMemorySize, GSMEM_BYTES);
    cudaFuncSetAttribute(xproj_v2,  cudaFuncAttributeMaxDynamicSharedMemorySize, 65536);

    // conversions: x -> [hi|lo] pair; all 4 weights -> single fp16 cast (one launch)
    cvt_pairA<<<(1024 * 1024) / 256, 256>>>(x, x2, 10);
    {
        int q0 = 4096 * 1024 / 4, q1 = 1024 * 2048 / 4,
            q2 = 2048 * 1024 / 4, q3 = 1024 * 2048 / 4;
        int qt = q0 + q1 + q2 + q3;
        cvt_cast4<<<(qt + 255) / 256, 256>>>(in_proj, wi2, q0,
                                             gate_w1, gw1b, q1,
                                             gate_w2, gw2b, q2,
                                             out_proj, wob, q3);
    }

    // in_proj: xz[1024,4096] = x @ in_proj_w.T  (A pair Kp=2048, B wraps at 1024)
    gemm_fp16<<<dim3(32, 8, 1), 128, GSMEM_BYTES>>>(x2, wi2, 2048, 2048, 1024, 15,
                                                    xz, 4096, 0,
                                                    nullptr, 0, nullptr, nullptr, 0);

    // merged per-scale pipeline (all 3 scales per launch)
    conv_silu_all<<<(T_ALL * DI) / 256, 256>>>(xz, conv_w, conv_b, xcA);
    xproj_v2<<<T_ALL / 8, 256, 65536>>>(xcA, xproj_w, projA);
    dtproj_v2<<<(T_ALL / 64) * 8, 256>>>(projA, dtproj_w, dtproj_b, dtA);
    scan_all<<<384, 256>>>(dtA, projA, xcA, D_param, o0, o1, o2);

    fuse_kernel<<<(T_LEN * DI) / 256, 256>>>(o0, o1, o2, sw, fused, ctx2);

    // gate1: split-K x2 over A pair (4096 cols); B single 2048-wide, no wrap
    gemm_fp16<<<dim3(8, 8, 2), 128, GSMEM_BYTES>>>(ctx2, gw1b, 2048, 4096, 2048, 31,
                                                   scr, DIM_, (size_t)T_LEN * DIM_,
                                                   nullptr, 0, nullptr, nullptr, 0);
    comb_silu_hi<<<(T_LEN * DIM_) / 256, 256>>>(scr, scr + T_LEN * DIM_, g1b);

    // gate2: A hi-only (Kp=1024); epilogue -> u2 pair (K=2048)
    gemm_fp16<<<dim3(16, 8, 1), 128, GSMEM_BYTES>>>(g1b, gw2b, 1024, 1024, 1024, 15,
                                                    nullptr, 0, 0,
                                                    u2, 2048, fused, xz, 2);

    // out_proj: split-K x2 over A pair (4096 cols); B single 2048-wide
    gemm_fp16<<<dim3(8, 8, 2), 128, GSMEM_BYTES>>>(u2, wob, 2048, 4096, 2048, 31,
                                                   scr, DIM_, (size_t)T_LEN * DIM_,
                                                   nullptr, 0, nullptr, nullptr, 0);

    ln_kernel<<<T_LEN, 256>>>(scr, scr + T_LEN * DIM_, x, ln_g, ln_b, out);
}